// round 14
// baseline (speedup 1.0000x reference)
#include <cuda_runtime.h>
#include <cuda_fp16.h>
#include <cstdint>
#include <math.h>

// Problem constants
#define NN   4
#define II   64
#define CCH  256
#define GG   8
#define CG   32
#define KS   9
#define HH   48
#define HWQ  (48*48)   // 2304
#define HD   40
#define DD   (40*40)   // 1600
#define PW   56        // padded width/height (48 + 2*4)
#define PHW  (56*56)   // 3136

// ---------------- scratch (device globals; no allocation allowed) -----------
__device__ __align__(128) __half g_xh2[NN*GG*PHW*64];  // padded channel-last xh (fp16)
__device__ __align__(128) __half g_wS[GG*81*160*64];   // [g][tap][row(5conv*32)][ci]
__device__ __align__(128) __half g_wV[GG*81*64*64];    // [g][tap][row(2conv*32)][ci]
__device__ __align__(128) float g_q [NN*CCH*HWQ];
__device__ __align__(128) float g_k [NN*CCH*DD];
__device__ __align__(128) float g_v [NN*CCH*DD];
__device__ __align__(128) float g_gp[4][NN*CCH*HWQ];

// FFMA-only exp for softmax
__device__ __forceinline__ float fastexp(float x) {
    float z = fmaxf(x * 1.4426950408889634f, -120.f);
    float t = z + 12582912.f;
    int   e = __float_as_int(t) - 0x4B400000;
    float f = z - (t - 12582912.f);
    float p = fmaf(f, 0.0013333558f, 0.0096181291f);
    p = fmaf(f, p, 0.0555041087f);
    p = fmaf(f, p, 0.2402265069f);
    p = fmaf(f, p, 0.69314718056f);
    p = fmaf(f, p, 1.0f);
    return __int_as_float(__float_as_int(p) + (e << 23));
}
__device__ __forceinline__ float ftanh(float x) {
    float t; asm("tanh.approx.f32 %0, %1;" : "=f"(t) : "f"(x)); return t;
}
__device__ __forceinline__ float sigm(float x) {
    return fmaf(ftanh(x * 0.5f), 0.5f, 0.5f);
}

// m16n8k8 tf32 mma.sync (attention)
__device__ __forceinline__ void mma8(float* c, const uint32_t* a,
                                     uint32_t b0, uint32_t b1) {
    asm volatile(
        "mma.sync.aligned.m16n8k8.row.col.f32.tf32.tf32.f32 "
        "{%0,%1,%2,%3}, {%4,%5,%6,%7}, {%8,%9}, {%0,%1,%2,%3};"
        : "+f"(c[0]), "+f"(c[1]), "+f"(c[2]), "+f"(c[3])
        : "r"(a[0]), "r"(a[1]), "r"(a[2]), "r"(a[3]), "r"(b0), "r"(b1));
}
// m16n8k16 fp16 mma.sync with fp32 accumulate (convs)
__device__ __forceinline__ void mma16(float* c, const uint32_t* a,
                                      uint32_t b0, uint32_t b1) {
    asm volatile(
        "mma.sync.aligned.m16n8k16.row.col.f32.f16.f16.f32 "
        "{%0,%1,%2,%3}, {%4,%5,%6,%7}, {%8,%9}, {%0,%1,%2,%3};"
        : "+f"(c[0]), "+f"(c[1]), "+f"(c[2]), "+f"(c[3])
        : "r"(a[0]), "r"(a[1]), "r"(a[2]), "r"(a[3]), "r"(b0), "r"(b1));
}
__device__ __forceinline__ void ldsm4(uint32_t* r, uint32_t addr) {
    asm volatile("ldmatrix.sync.aligned.m8n8.x4.shared.b16 {%0,%1,%2,%3}, [%4];"
        : "=r"(r[0]), "=r"(r[1]), "=r"(r[2]), "=r"(r[3]) : "r"(addr));
}
__device__ __forceinline__ void cp16(uint32_t dst, const void* src) {
    asm volatile("cp.async.cg.shared.global [%0], [%1], 16;" :: "r"(dst), "l"(src));
}
__device__ __forceinline__ uint32_t smem_u32(const void* p) {
    uint32_t a;
    asm("{ .reg .u64 t; cvta.to.shared.u64 t, %1; cvt.u32.u64 %0, t; }" : "=r"(a) : "l"(p));
    return a;
}

// ---------------- 0: zero padded xh buffer ----------------------------------
__global__ void zero_xh2_kernel() {
    size_t total16 = (size_t)NN*GG*PHW*64*2/16;
    uint4* p = reinterpret_cast<uint4*>(g_xh2);
    for (size_t i = (size_t)blockIdx.x*blockDim.x + threadIdx.x; i < total16;
         i += (size_t)gridDim.x*blockDim.x)
        p[i] = make_uint4(0u,0u,0u,0u);
}

// ---------------- 0b: weight transpose via smem tile (coalesced, fp16) ------
__global__ __launch_bounds__(256)
void wtrans_kernel(const float* __restrict__ Wq, const float* __restrict__ Wi,
                   const float* __restrict__ Wf, const float* __restrict__ Wg,
                   const float* __restrict__ Wo, const float* __restrict__ Wk,
                   const float* __restrict__ Wv)
{
    __shared__ float sm[5184];
    int b = blockIdx.x;          // 0..1791
    int g = b / 224;
    int r = b % 224;
    int tid = threadIdx.x;

    const float* W;
    __half* dst;
    int row, NCr, rr;
    if (r < 160) {
        int j = r >> 5;
        W = (j==0)?Wq:(j==1)?Wi:(j==2)?Wf:(j==3)?Wg:Wo;
        row = r & 31; dst = g_wS; NCr = 160; rr = r;
    } else {
        int r2 = r - 160;
        W = (r2 < 32) ? Wk : Wv;
        row = r2 & 31; dst = g_wV; NCr = 64; rr = r2;
    }
    const float* src = W + (size_t)(g*32 + row)*5184;
    for (int u = tid; u < 5184; u += 256) sm[u] = src[u];
    __syncthreads();
    for (int u = tid; u < 5184; u += 256) {
        int k = u >> 6, ci = u & 63;
        dst[((size_t)(g*81 + k)*NCr + rr)*64 + ci] = __float2half_rn(sm[ci*81 + k]);
    }
}

// ---------------- 1: projection + build padded channel-last xh (fp16) -------
__global__ __launch_bounds__(256)
void proj_kernel(const float* __restrict__ inp, const float* __restrict__ h,
                 const float* __restrict__ Wx, const float* __restrict__ Wxg)
{
    __shared__ float ws[8*320];
    int n  = blockIdx.z;
    int c0 = blockIdx.y * 8;
    int p0 = blockIdx.x * 256;
    int tid = threadIdx.x;

    for (int idx = tid; idx < 8*320; idx += 256) {
        int j = idx / 320, ic = idx - j*320;
        ws[idx] = (ic < 64) ? Wx[(c0+j)*64 + ic] : Wxg[(c0+j)*256 + (ic-64)];
    }
    __syncthreads();

    int p = p0 + tid;
    float acc[8];
#pragma unroll
    for (int j = 0; j < 8; ++j) acc[j] = 0.f;

    const float* ib = inp + (size_t)n*II*HWQ + p;
    const float* hb = h   + (size_t)n*CCH*HWQ + p;

#pragma unroll 4
    for (int ic = 0; ic < 64; ++ic) {
        float v = ib[ic*HWQ];
#pragma unroll
        for (int j = 0; j < 8; ++j) acc[j] = fmaf(ws[j*320+ic], v, acc[j]);
    }
#pragma unroll 4
    for (int ic = 0; ic < 256; ++ic) {
        float v = hb[ic*HWQ];
#pragma unroll
        for (int j = 0; j < 8; ++j) acc[j] = fmaf(ws[j*320+64+ic], v, acc[j]);
    }

    int y = p / 48, x = p - y*48;
    int g = c0 >> 5;
    __half* xb = g_xh2 + ((size_t)(n*GG + g)*PHW + (y+4)*PW + (x+4))*64;
#pragma unroll
    for (int j = 0; j < 8; ++j) {
        int cg = (c0 + j) & 31;
        xb[cg]      = __float2half_rn(acc[j]);
        xb[32 + cg] = __float2half_rn(hb[(c0+j)*HWQ]);
    }
}

// ---------------- 2a: SAME grouped conv (q + 4 gates), fp16 mma + ldmatrix --
#define ITH (24*24*72)          // halves
#define SMEM_S (ITH*2 + 3*160*40*2)   // 121344 bytes
__global__ __launch_bounds__(256, 1)
void conv_same_kernel()
{
    extern __shared__ __half smh[];
    __half* IT = smh;

    const int tid = threadIdx.x;
    const int wid = tid >> 5, lane = tid & 31;
    const int gid = lane >> 2, tig = lane & 3;
    const int my0 = (wid >> 1) * 4;
    const int nb  = (wid & 1) * 80;

    const int g  = blockIdx.y;
    const int n  = blockIdx.z;
    const int x0 = (blockIdx.x % 3) * 16;
    const int y0 = (blockIdx.x / 3) * 16;

    float* outs[5] = {g_q, g_gp[0], g_gp[1], g_gp[2], g_gp[3]};

    const __half* xsrc = g_xh2 + (size_t)(n*GG + g)*PHW*64;
    const __half* wg   = g_wS + (size_t)g*81*160*64;
    const uint32_t itb   = smem_u32(smh);
    const uint32_t smemB = itb + ITH*2;

    // ldmatrix per-lane offsets (bytes)
    const uint32_t laneA = 2u * ((((lane >> 3) & 1)*8 + (lane & 7))*72 + (lane >> 4)*8);
    const uint32_t laneB = 2u * ((((lane >> 4) & 1)*8 + (lane & 7))*40 + ((lane >> 3) & 1)*8);

    auto stageB = [&](int t, int buf) {
        int kk = t >> 1, ci0 = (t & 1) * 32;
        const __half* wsrc = wg + (size_t)kk*160*64 + ci0;
        uint32_t bbase = smemB + (uint32_t)buf*(160*40*2);
        for (int u = tid; u < 160*4; u += 256) {
            int n2 = u >> 2, seg = u & 3;
            cp16(bbase + (uint32_t)(n2*80 + seg*16), wsrc + n2*64 + seg*8);
        }
    };

    stageB(0, 0);
    asm volatile("cp.async.commit_group;" ::: "memory");
    stageB(1, 1);
    asm volatile("cp.async.commit_group;" ::: "memory");

    for (int u = tid; u < 24*24*8; u += 256) {
        int f4 = u & 7, pos = u >> 3;
        int yy = pos / 24, xx = pos - yy*24;
        int gy = min(y0 + yy, 55), gx = min(x0 + xx, 55);
        float4 v = *reinterpret_cast<const float4*>(xsrc + (size_t)(gy*PW + gx)*64 + f4*8);
        *reinterpret_cast<float4*>(IT + pos*72 + f4*8) = v;
    }

    float acc[4][10][4];
#pragma unroll
    for (int mi = 0; mi < 4; ++mi)
#pragma unroll
        for (int nj = 0; nj < 10; ++nj)
#pragma unroll
            for (int r = 0; r < 4; ++r) acc[mi][nj][r] = 0.f;

    for (int t = 0; t < 162; ++t) {
        if (t == 161) asm volatile("cp.async.wait_group 0;" ::: "memory");
        else          asm volatile("cp.async.wait_group 1;" ::: "memory");
        __syncthreads();
        if (t + 2 < 162) {
            stageB(t+2, (t+2) % 3);
            asm volatile("cp.async.commit_group;" ::: "memory");
        }

        const int kk = t >> 1, ci0 = (t & 1) * 32;
        const int ky = kk / 9, kx = kk - ky*9;
        const uint32_t bB = smemB + (uint32_t)(t % 3)*(160*40*2);

#pragma unroll
        for (int ks = 0; ks < 2; ++ks) {
            const int kh0 = ci0 + ks*16;
            uint32_t a[4][4];
#pragma unroll
            for (int mi = 0; mi < 4; ++mi)
                ldsm4(a[mi], itb + 2u*(uint32_t)(((my0 + mi + ky)*24 + kx)*72 + kh0) + laneA);
#pragma unroll
            for (int nj2 = 0; nj2 < 5; ++nj2) {
                uint32_t b[4];
                ldsm4(b, bB + 2u*(uint32_t)((nb + nj2*16)*40 + ks*16) + laneB);
#pragma unroll
                for (int mi = 0; mi < 4; ++mi) {
                    mma16(acc[mi][2*nj2],   a[mi], b[0], b[1]);
                    mma16(acc[mi][2*nj2+1], a[mi], b[2], b[3]);
                }
            }
        }
    }

#pragma unroll
    for (int mi = 0; mi < 4; ++mi) {
        int y = y0 + my0 + mi;
#pragma unroll
        for (int nj = 0; nj < 10; ++nj)
#pragma unroll
            for (int r = 0; r < 4; ++r) {
                int x = x0 + gid + ((r >> 1) << 3);
                int nc = nb + nj*8 + tig*2 + (r & 1);
                int conv = nc >> 5, cg = nc & 31;
                outs[conv][((size_t)(n*CCH + g*32 + cg)*48 + y)*48 + x] = acc[mi][nj][r];
            }
    }
}

// ---------------- 2b: VALID grouped conv (k, v), fp16 mma + ldmatrix --------
#define SMEM_V (2*ITH*2 + 3*64*40*2)  // 181248 bytes
__global__ __launch_bounds__(256, 1)
void conv_valid_kernel()
{
    extern __shared__ __half smh[];

    const int tid = threadIdx.x;
    const int wid = tid >> 5, lane = tid & 31;
    const int gid = lane >> 2, tig = lane & 3;
    const int bw  = wid >> 2;
    const int my0 = (wid & 3) * 4;

    const int g  = blockIdx.y;
    const int n0 = blockIdx.z * 2;
    const int x0 = (blockIdx.x % 3) * 16;
    const int y0 = (blockIdx.x / 3) * 16;

    const __half* wg = g_wV + (size_t)g*81*64*64;
    const uint32_t smb   = smem_u32(smh);
    const uint32_t smemB = smb + 2*ITH*2;

    const uint32_t laneA = 2u * ((((lane >> 3) & 1)*8 + (lane & 7))*72 + (lane >> 4)*8);
    const uint32_t laneB = 2u * ((((lane >> 4) & 1)*8 + (lane & 7))*40 + ((lane >> 3) & 1)*8);

    auto stageB = [&](int t, int buf) {
        int kk = t >> 1, ci0 = (t & 1) * 32;
        const __half* wsrc = wg + (size_t)kk*64*64 + ci0;
        uint32_t bbase = smemB + (uint32_t)buf*(64*40*2);
        for (int u = tid; u < 64*4; u += 256) {
            int n2 = u >> 2, seg = u & 3;
            cp16(bbase + (uint32_t)(n2*80 + seg*16), wsrc + n2*64 + seg*8);
        }
    };

    stageB(0, 0);
    asm volatile("cp.async.commit_group;" ::: "memory");
    stageB(1, 1);
    asm volatile("cp.async.commit_group;" ::: "memory");

    for (int u = tid; u < 2*24*24*8; u += 256) {
        int b2 = u / (24*24*8);
        int u2 = u - b2*(24*24*8);
        int f4 = u2 & 7, pos = u2 >> 3;
        int yy = pos / 24, xx = pos - yy*24;
        int gy = min(y0 + 4 + yy, 55), gx = min(x0 + 4 + xx, 55);
        const __half* xsrc = g_xh2 + (size_t)((n0+b2)*GG + g)*PHW*64;
        float4 v = *reinterpret_cast<const float4*>(xsrc + (size_t)(gy*PW + gx)*64 + f4*8);
        *reinterpret_cast<float4*>(smh + b2*ITH + pos*72 + f4*8) = v;
    }

    const uint32_t itb = smb + (uint32_t)bw*ITH*2;

    float acc[4][8][4];
#pragma unroll
    for (int mi = 0; mi < 4; ++mi)
#pragma unroll
        for (int nj = 0; nj < 8; ++nj)
#pragma unroll
            for (int r = 0; r < 4; ++r) acc[mi][nj][r] = 0.f;

    for (int t = 0; t < 162; ++t) {
        if (t == 161) asm volatile("cp.async.wait_group 0;" ::: "memory");
        else          asm volatile("cp.async.wait_group 1;" ::: "memory");
        __syncthreads();
        if (t + 2 < 162) {
            stageB(t+2, (t+2) % 3);
            asm volatile("cp.async.commit_group;" ::: "memory");
        }

        const int kk = t >> 1, ci0 = (t & 1) * 32;
        const int ky = kk / 9, kx = kk - ky*9;
        const uint32_t bB = smemB + (uint32_t)(t % 3)*(64*40*2);

#pragma unroll
        for (int ks = 0; ks < 2; ++ks) {
            const int kh0 = ci0 + ks*16;
            uint32_t a[4][4];
#pragma unroll
            for (int mi = 0; mi < 4; ++mi)
                ldsm4(a[mi], itb + 2u*(uint32_t)(((my0 + mi + ky)*24 + kx)*72 + kh0) + laneA);
#pragma unroll
            for (int nj2 = 0; nj2 < 4; ++nj2) {
                uint32_t b[4];
                ldsm4(b, bB + 2u*(uint32_t)((nj2*16)*40 + ks*16) + laneB);
#pragma unroll
                for (int mi = 0; mi < 4; ++mi) {
                    mma16(acc[mi][2*nj2],   a[mi], b[0], b[1]);
                    mma16(acc[mi][2*nj2+1], a[mi], b[2], b[3]);
                }
            }
        }
    }

    const int n = n0 + bw;
#pragma unroll
    for (int mi = 0; mi < 4; ++mi) {
        int y = y0 + my0 + mi;
        if (y >= 40) continue;
#pragma unroll
        for (int nj = 0; nj < 8; ++nj)
#pragma unroll
            for (int r = 0; r < 4; ++r) {
                int x = x0 + gid + ((r >> 1) << 3);
                if (x < 40) {
                    int nc = nj*8 + tig*2 + (r & 1);
                    float* outp = (nc < 32) ? g_k : g_v;
                    int cg = nc & 31;
                    outp[((size_t)(n*CCH + g*32 + cg)*40 + y)*40 + x] = acc[mi][nj][r];
                }
            }
    }
}

// ---------------- 3: attention (mma, pipelined) + fused gates ---------------
#define LSP  1604            // logits row stride
#define CHW  320             // staged K/V chunk width
#define CHP  324             // chunk row stride
// ls + qs + 3 kv buffers; os & gate weights alias kv
#define ATTN_SMEM ((16*LSP + 16*36 + 3*32*CHP) * 4)   // 229376

__global__ __launch_bounds__(256)
void attn_kernel(const float* __restrict__ tau,
                 const float* __restrict__ Wa_i, const float* __restrict__ Wa_f,
                 const float* __restrict__ Wa_g, const float* __restrict__ Wa_o,
                 const float* __restrict__ b_i,  const float* __restrict__ b_f,
                 const float* __restrict__ b_g,  const float* __restrict__ b_o,
                 const float* __restrict__ c_prev, float* __restrict__ outp)
{
    extern __shared__ float smf[];
    float* ls  = smf;                 // [16][LSP]
    float* qs  = ls + 16*LSP;         // [16][36]   (reused as oq later)
    float* kvb = qs + 16*36;          // 3 x [32][CHP]

    int bz = blockIdx.x;
    int qt = bz % 144;
    int g  = (bz / 144) & 7;
    int n  = bz / 1152;
    int q0 = qt * 16;

    const float* qb = g_q + ((size_t)(n*CCH) + g*32)*HWQ + q0;
    const float* kb = g_k + ((size_t)(n*CCH) + g*32)*DD;
    const float* vb = g_v + ((size_t)(n*CCH) + g*32)*DD;
    int tid = threadIdx.x;
    int wid = tid >> 5, lane = tid & 31;
    int gid = lane >> 2, tig = lane & 3;
    uint32_t kvaddr = smem_u32(kvb);

    auto stage = [&](int c, int buf) {
        const float* src = ((c < 5) ? kb : vb) + (c % 5)*CHW;
        uint32_t bbase = kvaddr + (uint32_t)buf*(32*CHP*4);
        for (int u = tid; u < 32*80; u += 256) {
            int cc = u / 80, seg = u - cc*80;
            cp16(bbase + (uint32_t)(cc*CHP + seg*4)*4, src + (size_t)cc*DD + seg*4);
        }
    };

    stage(0, 0);
    asm volatile("cp.async.commit_group;" ::: "memory");
    stage(1, 1);
    asm volatile("cp.async.commit_group;" ::: "memory");

    for (int idx = tid; idx < 512; idx += 256) {
        int qi = idx >> 5, c = idx & 31;
        qs[qi*36 + c] = qb[c*HWQ + qi];
    }
    float tg = tau[g];

    float acc2[4][4];
#pragma unroll
    for (int nj = 0; nj < 4; ++nj)
#pragma unroll
        for (int r = 0; r < 4; ++r) acc2[nj][r] = 0.f;

    for (int ch = 0; ch < 10; ++ch) {
        if (ch == 9) asm volatile("cp.async.wait_group 0;" ::: "memory");
        else         asm volatile("cp.async.wait_group 1;" ::: "memory");
        __syncthreads();
        if (ch + 2 < 10) {
            stage(ch+2, (ch+2) % 3);
            asm volatile("cp.async.commit_group;" ::: "memory");
        }

        const float* kv = kvb + (ch % 3)*(32*CHP);

        if (ch < 5) {
            // ---- phase 1: logits for chunk ch ----
            int d0 = ch*CHW;
            int nw = wid*40;
            float acc[5][4];
#pragma unroll
            for (int nj = 0; nj < 5; ++nj)
#pragma unroll
                for (int r = 0; r < 4; ++r) acc[nj][r] = 0.f;

#pragma unroll
            for (int ks = 0; ks < 4; ++ks) {
                int kbi = ks*8;
                uint32_t a[4];
                a[0] = __float_as_uint(qs[gid*36     + kbi + tig]);
                a[1] = __float_as_uint(qs[(gid+8)*36 + kbi + tig]);
                a[2] = __float_as_uint(qs[gid*36     + kbi + tig + 4]);
                a[3] = __float_as_uint(qs[(gid+8)*36 + kbi + tig + 4]);
#pragma unroll
                for (int nj = 0; nj < 5; ++nj) {
                    uint32_t b0 = __float_as_uint(kv[(kbi+tig)*CHP   + nw + nj*8 + gid]);
                    uint32_t b1 = __float_as_uint(kv[(kbi+tig+4)*CHP + nw + nj*8 + gid]);
                    mma8(acc[nj], a, b0, b1);
                }
            }
#pragma unroll
            for (int nj = 0; nj < 5; ++nj) {
                int d = d0 + nw + nj*8 + 2*tig;
                float2 lo = make_float2(acc[nj][0]*tg, acc[nj][1]*tg);
                float2 hi = make_float2(acc[nj][2]*tg, acc[nj][3]*tg);
                *reinterpret_cast<float2*>(ls + gid*LSP     + d) = lo;
                *reinterpret_cast<float2*>(ls + (gid+8)*LSP + d) = hi;
            }
        } else {
            if (ch == 5) {
                // ---- softmax (all logits ready; V staging in flight) ----
                for (int q = wid; q < 16; q += 8) {
                    float* row = ls + q*LSP;
                    float m = -1e30f;
                    for (int d = lane; d < DD; d += 32) m = fmaxf(m, row[d]);
#pragma unroll
                    for (int off = 16; off; off >>= 1) m = fmaxf(m, __shfl_xor_sync(~0u, m, off));
                    float s = 0.f;
                    for (int d = lane; d < DD; d += 32) { float e = fastexp(row[d]-m); row[d] = e; s += e; }
#pragma unroll
                    for (int off = 16; off; off >>= 1) s += __shfl_xor_sync(~0u, s, off);
                    float inv = 1.f / s;
                    for (int d = lane; d < DD; d += 32) row[d] *= inv;
                }
                __syncthreads();
            }
            // ---- phase 2: O partial for V chunk (ch-5) ----
            int d0 = (ch-5)*CHW;
#pragma unroll
            for (int ks = 0; ks < 5; ++ks) {
                int kl = wid*40 + ks*8;
                uint32_t a[4];
                a[0] = __float_as_uint(ls[gid*LSP     + d0 + kl + tig]);
                a[1] = __float_as_uint(ls[(gid+8)*LSP + d0 + kl + tig]);
                a[2] = __float_as_uint(ls[gid*LSP     + d0 + kl + tig + 4]);
                a[3] = __float_as_uint(ls[(gid+8)*LSP + d0 + kl + tig + 4]);
#pragma unroll
                for (int nj = 0; nj < 4; ++nj) {
                    uint32_t b0 = __float_as_uint(kv[(nj*8+gid)*CHP + kl + tig]);
                    uint32_t b1 = __float_as_uint(kv[(nj*8+gid)*CHP + kl + tig + 4]);
                    mma8(acc2[nj], a, b0, b1);
                }
            }
        }
    }
    __syncthreads();   // all mma done; kv region free for reuse

    // os aliases kv buffers
    float* os  = kvb;              // [8][16][33] = 4224 floats
    float* wsm = kvb + 4352;       // 4*1024
    float* bsm = wsm + 4096;       // 4*32

#pragma unroll
    for (int nj = 0; nj < 4; ++nj)
#pragma unroll
        for (int r = 0; r < 4; ++r) {
            int q = gid + ((r >> 1) << 3);
            int c = nj*8 + tig*2 + (r & 1);
            os[(wid*16 + q)*33 + c] = acc2[nj][r];
        }
    // gate weights/biases
    for (int u = tid; u < 1024; u += 256) {
        int e = u >> 8, off = (u & 255)*4;
        const float* Wa = (e==0)?Wa_i:(e==1)?Wa_f:(e==2)?Wa_g:Wa_o;
        *reinterpret_cast<float4*>(wsm + e*1024 + off) =
            *reinterpret_cast<const float4*>(Wa + (size_t)g*1024 + off);
    }
    if (tid < 128) {
        int e = tid >> 5, c = tid & 31;
        const float* bb = (e==0)?b_i:(e==1)?b_f:(e==2)?b_g:b_o;
        bsm[tid] = bb[g*32 + c];
    }
    __syncthreads();

    // reduce partials into oq (reuse qs)
    float* oq = qs;
    for (int u = tid; u < 512; u += 256) {
        int q = u >> 5, c = u & 31;
        float s = 0.f;
#pragma unroll
        for (int w = 0; w < 8; ++w) s += os[(w*16 + q)*33 + c];
        oq[q*33 + c] = s;
    }
    __syncthreads();

    // fused gates + cell update
    for (int u = tid; u < 512; u += 256) {
        int q = u & 15, c = u >> 4;
        float a0 = bsm[c], a1 = bsm[32+c], a2 = bsm[64+c], a3 = bsm[96+c];
#pragma unroll 8
        for (int cc = 0; cc < 32; ++cc) {
            float o = oq[q*33 + cc];
            a0 = fmaf(wsm[        c*32 + cc], o, a0);
            a1 = fmaf(wsm[1024 + c*32 + cc], o, a1);
            a2 = fmaf(wsm[2048 + c*32 + cc], o, a2);
            a3 = fmaf(wsm[3072 + c*32 + cc], o, a3);
        }
        size_t off = ((size_t)(n*CCH) + g*32 + c)*HWQ + q0 + q;
        float gi = sigm (a0 + g_gp[0][off]);
        float gf = sigm (a1 + g_gp[1][off]);
        float gg = ftanh(a2 + g_gp[2][off]);
        float go = sigm (a3 + g_gp[3][off]);
        float cn = gf * c_prev[off] + gi * gg;
        outp[off] = go * ftanh(cn);
    }
}

// ---------------- launch ----------------------------------------------------
extern "C" void kernel_launch(void* const* d_in, const int* in_sizes, int n_in,
                              void* d_out, int out_size)
{
    (void)in_sizes; (void)n_in; (void)out_size;
    const float* inp    = (const float*)d_in[0];
    const float* h_prev = (const float*)d_in[1];
    const float* c_prev = (const float*)d_in[2];
    const float* Wx     = (const float*)d_in[3];
    const float* Wxg    = (const float*)d_in[4];
    const float* tau    = (const float*)d_in[5];
    const float* Wq     = (const float*)d_in[6];
    const float* Wk     = (const float*)d_in[7];
    const float* Wv     = (const float*)d_in[8];
    const float* Wa_i   = (const float*)d_in[9];
    const float* Wxh_i  = (const float*)d_in[10];
    const float* b_i    = (const float*)d_in[11];
    const float* Wa_f   = (const float*)d_in[12];
    const float* Wxh_f  = (const float*)d_in[13];
    const float* b_f    = (const float*)d_in[14];
    const float* Wa_g   = (const float*)d_in[15];
    const float* Wxh_g  = (const float*)d_in[16];
    const float* b_g    = (const float*)d_in[17];
    const float* Wa_o   = (const float*)d_in[18];
    const float* Wxh_o  = (const float*)d_in[19];
    const float* b_o    = (const float*)d_in[20];
    float* out = (float*)d_out;

    cudaFuncSetAttribute(attn_kernel,
                         cudaFuncAttributeMaxDynamicSharedMemorySize, ATTN_SMEM);
    cudaFuncSetAttribute(conv_same_kernel,
                         cudaFuncAttributeMaxDynamicSharedMemorySize, SMEM_S);
    cudaFuncSetAttribute(conv_valid_kernel,
                         cudaFuncAttributeMaxDynamicSharedMemorySize, SMEM_V);

    zero_xh2_kernel<<<2048, 256>>>();
    wtrans_kernel<<<GG*224, 256>>>(Wq, Wxh_i, Wxh_f, Wxh_g, Wxh_o, Wk, Wv);
    proj_kernel<<<dim3(9, 32, 4), 256>>>(inp, h_prev, Wx, Wxg);
    conv_same_kernel<<<dim3(9, 8, 4), 256, SMEM_S>>>();
    conv_valid_kernel<<<dim3(9, 8, 2), 256, SMEM_V>>>();
    attn_kernel<<<NN*GG*144, 256, ATTN_SMEM>>>(tau, Wa_i, Wa_f, Wa_g, Wa_o,
                                               b_i, b_f, b_g, b_o, c_prev, out);
}

// round 15
// speedup vs baseline: 1.0020x; 1.0020x over previous
#include <cuda_runtime.h>
#include <cuda_fp16.h>
#include <cstdint>
#include <math.h>

// Problem constants
#define NN   4
#define II   64
#define CCH  256
#define GG   8
#define CG   32
#define KS   9
#define HH   48
#define HWQ  (48*48)   // 2304
#define HD   40
#define DD   (40*40)   // 1600
#define PW   56        // padded width/height (48 + 2*4)
#define PHW  (56*56)   // 3136

// ---------------- scratch (device globals; no allocation allowed) -----------
__device__ __align__(128) __half g_xh2[NN*GG*PHW*64];  // padded channel-last xh (fp16)
__device__ __align__(128) __half g_wS[GG*81*160*64];   // [g][tap][row(5conv*32)][ci]
__device__ __align__(128) __half g_wV[GG*81*64*64];    // [g][tap][row(2conv*32)][ci]
__device__ __align__(128) float g_q [NN*CCH*HWQ];
__device__ __align__(128) float g_k [NN*CCH*DD];
__device__ __align__(128) float g_v [NN*CCH*DD];
__device__ __align__(128) float g_gp[4][NN*CCH*HWQ];

// FFMA-only exp for softmax
__device__ __forceinline__ float fastexp(float x) {
    float z = fmaxf(x * 1.4426950408889634f, -120.f);
    float t = z + 12582912.f;
    int   e = __float_as_int(t) - 0x4B400000;
    float f = z - (t - 12582912.f);
    float p = fmaf(f, 0.0013333558f, 0.0096181291f);
    p = fmaf(f, p, 0.0555041087f);
    p = fmaf(f, p, 0.2402265069f);
    p = fmaf(f, p, 0.69314718056f);
    p = fmaf(f, p, 1.0f);
    return __int_as_float(__float_as_int(p) + (e << 23));
}
__device__ __forceinline__ float ftanh(float x) {
    float t; asm("tanh.approx.f32 %0, %1;" : "=f"(t) : "f"(x)); return t;
}
__device__ __forceinline__ float sigm(float x) {
    return fmaf(ftanh(x * 0.5f), 0.5f, 0.5f);
}

// m16n8k8 tf32 mma.sync (attention)
__device__ __forceinline__ void mma8(float* c, const uint32_t* a,
                                     uint32_t b0, uint32_t b1) {
    asm volatile(
        "mma.sync.aligned.m16n8k8.row.col.f32.tf32.tf32.f32 "
        "{%0,%1,%2,%3}, {%4,%5,%6,%7}, {%8,%9}, {%0,%1,%2,%3};"
        : "+f"(c[0]), "+f"(c[1]), "+f"(c[2]), "+f"(c[3])
        : "r"(a[0]), "r"(a[1]), "r"(a[2]), "r"(a[3]), "r"(b0), "r"(b1));
}
// m16n8k16 fp16 mma.sync with fp32 accumulate (convs)
__device__ __forceinline__ void mma16(float* c, const uint32_t* a,
                                      uint32_t b0, uint32_t b1) {
    asm volatile(
        "mma.sync.aligned.m16n8k16.row.col.f32.f16.f16.f32 "
        "{%0,%1,%2,%3}, {%4,%5,%6,%7}, {%8,%9}, {%0,%1,%2,%3};"
        : "+f"(c[0]), "+f"(c[1]), "+f"(c[2]), "+f"(c[3])
        : "r"(a[0]), "r"(a[1]), "r"(a[2]), "r"(a[3]), "r"(b0), "r"(b1));
}
__device__ __forceinline__ void ldsm4(uint32_t* r, uint32_t addr) {
    asm volatile("ldmatrix.sync.aligned.m8n8.x4.shared.b16 {%0,%1,%2,%3}, [%4];"
        : "=r"(r[0]), "=r"(r[1]), "=r"(r[2]), "=r"(r[3]) : "r"(addr));
}
__device__ __forceinline__ void cp16(uint32_t dst, const void* src) {
    asm volatile("cp.async.cg.shared.global [%0], [%1], 16;" :: "r"(dst), "l"(src));
}
__device__ __forceinline__ uint32_t smem_u32(const void* p) {
    uint32_t a;
    asm("{ .reg .u64 t; cvta.to.shared.u64 t, %1; cvt.u32.u64 %0, t; }" : "=r"(a) : "l"(p));
    return a;
}

// ---------------- 0: zero padded xh buffer ----------------------------------
__global__ void zero_xh2_kernel() {
    size_t total16 = (size_t)NN*GG*PHW*64*2/16;
    uint4* p = reinterpret_cast<uint4*>(g_xh2);
    for (size_t i = (size_t)blockIdx.x*blockDim.x + threadIdx.x; i < total16;
         i += (size_t)gridDim.x*blockDim.x)
        p[i] = make_uint4(0u,0u,0u,0u);
}

// ---------------- 0b: weight transpose via smem tile (coalesced, fp16) ------
__global__ __launch_bounds__(256)
void wtrans_kernel(const float* __restrict__ Wq, const float* __restrict__ Wi,
                   const float* __restrict__ Wf, const float* __restrict__ Wg,
                   const float* __restrict__ Wo, const float* __restrict__ Wk,
                   const float* __restrict__ Wv)
{
    __shared__ float sm[5184];
    int b = blockIdx.x;          // 0..1791
    int g = b / 224;
    int r = b % 224;
    int tid = threadIdx.x;

    const float* W;
    __half* dst;
    int row, NCr, rr;
    if (r < 160) {
        int j = r >> 5;
        W = (j==0)?Wq:(j==1)?Wi:(j==2)?Wf:(j==3)?Wg:Wo;
        row = r & 31; dst = g_wS; NCr = 160; rr = r;
    } else {
        int r2 = r - 160;
        W = (r2 < 32) ? Wk : Wv;
        row = r2 & 31; dst = g_wV; NCr = 64; rr = r2;
    }
    const float* src = W + (size_t)(g*32 + row)*5184;
    for (int u = tid; u < 5184; u += 256) sm[u] = src[u];
    __syncthreads();
    for (int u = tid; u < 5184; u += 256) {
        int k = u >> 6, ci = u & 63;
        dst[((size_t)(g*81 + k)*NCr + rr)*64 + ci] = __float2half_rn(sm[ci*81 + k]);
    }
}

// ---------------- 1: projection + build padded channel-last xh (fp16) -------
__global__ __launch_bounds__(256)
void proj_kernel(const float* __restrict__ inp, const float* __restrict__ h,
                 const float* __restrict__ Wx, const float* __restrict__ Wxg)
{
    __shared__ float ws[8*320];
    int n  = blockIdx.z;
    int c0 = blockIdx.y * 8;
    int p0 = blockIdx.x * 256;
    int tid = threadIdx.x;

    for (int idx = tid; idx < 8*320; idx += 256) {
        int j = idx / 320, ic = idx - j*320;
        ws[idx] = (ic < 64) ? Wx[(c0+j)*64 + ic] : Wxg[(c0+j)*256 + (ic-64)];
    }
    __syncthreads();

    int p = p0 + tid;
    float acc[8];
#pragma unroll
    for (int j = 0; j < 8; ++j) acc[j] = 0.f;

    const float* ib = inp + (size_t)n*II*HWQ + p;
    const float* hb = h   + (size_t)n*CCH*HWQ + p;

#pragma unroll 4
    for (int ic = 0; ic < 64; ++ic) {
        float v = ib[ic*HWQ];
#pragma unroll
        for (int j = 0; j < 8; ++j) acc[j] = fmaf(ws[j*320+ic], v, acc[j]);
    }
#pragma unroll 4
    for (int ic = 0; ic < 256; ++ic) {
        float v = hb[ic*HWQ];
#pragma unroll
        for (int j = 0; j < 8; ++j) acc[j] = fmaf(ws[j*320+64+ic], v, acc[j]);
    }

    int y = p / 48, x = p - y*48;
    int g = c0 >> 5;
    __half* xb = g_xh2 + ((size_t)(n*GG + g)*PHW + (y+4)*PW + (x+4))*64;
#pragma unroll
    for (int j = 0; j < 8; ++j) {
        int cg = (c0 + j) & 31;
        xb[cg]      = __float2half_rn(acc[j]);
        xb[32 + cg] = __float2half_rn(hb[(c0+j)*HWQ]);
    }
}

// ---------------- 2a: SAME grouped conv (q + 4 gates), fp16 mma + ldmatrix --
#define ITH (24*24*72)          // halves
#define SMEM_S (ITH*2 + 3*160*40*2)   // 121344 bytes
__global__ __launch_bounds__(256, 1)
void conv_same_kernel()
{
    extern __shared__ __half smh[];
    __half* IT = smh;

    const int tid = threadIdx.x;
    const int wid = tid >> 5, lane = tid & 31;
    const int gid = lane >> 2, tig = lane & 3;
    const int my0 = (wid >> 1) * 4;
    const int nb  = (wid & 1) * 80;

    const int g  = blockIdx.y;
    const int n  = blockIdx.z;
    const int x0 = (blockIdx.x % 3) * 16;
    const int y0 = (blockIdx.x / 3) * 16;

    float* outs[5] = {g_q, g_gp[0], g_gp[1], g_gp[2], g_gp[3]};

    const __half* xsrc = g_xh2 + (size_t)(n*GG + g)*PHW*64;
    const __half* wg   = g_wS + (size_t)g*81*160*64;
    const uint32_t itb   = smem_u32(smh);
    const uint32_t smemB = itb + ITH*2;

    // ldmatrix per-lane offsets (bytes)
    const uint32_t laneA = 2u * ((((lane >> 3) & 1)*8 + (lane & 7))*72 + (lane >> 4)*8);
    const uint32_t laneB = 2u * ((((lane >> 4) & 1)*8 + (lane & 7))*40 + ((lane >> 3) & 1)*8);

    auto stageB = [&](int t, int buf) {
        int kk = t >> 1, ci0 = (t & 1) * 32;
        const __half* wsrc = wg + (size_t)kk*160*64 + ci0;
        uint32_t bbase = smemB + (uint32_t)buf*(160*40*2);
        for (int u = tid; u < 160*4; u += 256) {
            int n2 = u >> 2, seg = u & 3;
            cp16(bbase + (uint32_t)(n2*80 + seg*16), wsrc + n2*64 + seg*8);
        }
    };

    stageB(0, 0);
    asm volatile("cp.async.commit_group;" ::: "memory");
    stageB(1, 1);
    asm volatile("cp.async.commit_group;" ::: "memory");

    for (int u = tid; u < 24*24*8; u += 256) {
        int f4 = u & 7, pos = u >> 3;
        int yy = pos / 24, xx = pos - yy*24;
        int gy = min(y0 + yy, 55), gx = min(x0 + xx, 55);
        float4 v = *reinterpret_cast<const float4*>(xsrc + (size_t)(gy*PW + gx)*64 + f4*8);
        *reinterpret_cast<float4*>(IT + pos*72 + f4*8) = v;
    }

    float acc[4][10][4];
#pragma unroll
    for (int mi = 0; mi < 4; ++mi)
#pragma unroll
        for (int nj = 0; nj < 10; ++nj)
#pragma unroll
            for (int r = 0; r < 4; ++r) acc[mi][nj][r] = 0.f;

    for (int t = 0; t < 162; ++t) {
        if (t == 161) asm volatile("cp.async.wait_group 0;" ::: "memory");
        else          asm volatile("cp.async.wait_group 1;" ::: "memory");
        __syncthreads();
        if (t + 2 < 162) {
            stageB(t+2, (t+2) % 3);
            asm volatile("cp.async.commit_group;" ::: "memory");
        }

        const int kk = t >> 1, ci0 = (t & 1) * 32;
        const int ky = kk / 9, kx = kk - ky*9;
        const uint32_t bB = smemB + (uint32_t)(t % 3)*(160*40*2);

#pragma unroll
        for (int ks = 0; ks < 2; ++ks) {
            const int kh0 = ci0 + ks*16;
            uint32_t a[4][4];
#pragma unroll
            for (int mi = 0; mi < 4; ++mi)
                ldsm4(a[mi], itb + 2u*(uint32_t)(((my0 + mi + ky)*24 + kx)*72 + kh0) + laneA);
#pragma unroll
            for (int nj2 = 0; nj2 < 5; ++nj2) {
                uint32_t b[4];
                ldsm4(b, bB + 2u*(uint32_t)((nb + nj2*16)*40 + ks*16) + laneB);
#pragma unroll
                for (int mi = 0; mi < 4; ++mi) {
                    mma16(acc[mi][2*nj2],   a[mi], b[0], b[1]);
                    mma16(acc[mi][2*nj2+1], a[mi], b[2], b[3]);
                }
            }
        }
    }

#pragma unroll
    for (int mi = 0; mi < 4; ++mi) {
        int y = y0 + my0 + mi;
#pragma unroll
        for (int nj = 0; nj < 10; ++nj)
#pragma unroll
            for (int r = 0; r < 4; ++r) {
                int x = x0 + gid + ((r >> 1) << 3);
                int nc = nb + nj*8 + tig*2 + (r & 1);
                int conv = nc >> 5, cg = nc & 31;
                outs[conv][((size_t)(n*CCH + g*32 + cg)*48 + y)*48 + x] = acc[mi][nj][r];
            }
    }
}

// ---------------- 2b: VALID grouped conv (k, v), fp16 mma + ldmatrix --------
#define SMEM_V (2*ITH*2 + 3*64*40*2)  // 181248 bytes
__global__ __launch_bounds__(256, 1)
void conv_valid_kernel()
{
    extern __shared__ __half smh[];

    const int tid = threadIdx.x;
    const int wid = tid >> 5, lane = tid & 31;
    const int gid = lane >> 2, tig = lane & 3;
    const int bw  = wid >> 2;
    const int my0 = (wid & 3) * 4;

    const int g  = blockIdx.y;
    const int n0 = blockIdx.z * 2;
    const int x0 = (blockIdx.x % 3) * 16;
    const int y0 = (blockIdx.x / 3) * 16;

    const __half* wg = g_wV + (size_t)g*81*64*64;
    const uint32_t smb   = smem_u32(smh);
    const uint32_t smemB = smb + 2*ITH*2;

    const uint32_t laneA = 2u * ((((lane >> 3) & 1)*8 + (lane & 7))*72 + (lane >> 4)*8);
    const uint32_t laneB = 2u * ((((lane >> 4) & 1)*8 + (lane & 7))*40 + ((lane >> 3) & 1)*8);

    auto stageB = [&](int t, int buf) {
        int kk = t >> 1, ci0 = (t & 1) * 32;
        const __half* wsrc = wg + (size_t)kk*64*64 + ci0;
        uint32_t bbase = smemB + (uint32_t)buf*(64*40*2);
        for (int u = tid; u < 64*4; u += 256) {
            int n2 = u >> 2, seg = u & 3;
            cp16(bbase + (uint32_t)(n2*80 + seg*16), wsrc + n2*64 + seg*8);
        }
    };

    stageB(0, 0);
    asm volatile("cp.async.commit_group;" ::: "memory");
    stageB(1, 1);
    asm volatile("cp.async.commit_group;" ::: "memory");

    for (int u = tid; u < 2*24*24*8; u += 256) {
        int b2 = u / (24*24*8);
        int u2 = u - b2*(24*24*8);
        int f4 = u2 & 7, pos = u2 >> 3;
        int yy = pos / 24, xx = pos - yy*24;
        int gy = min(y0 + 4 + yy, 55), gx = min(x0 + 4 + xx, 55);
        const __half* xsrc = g_xh2 + (size_t)((n0+b2)*GG + g)*PHW*64;
        float4 v = *reinterpret_cast<const float4*>(xsrc + (size_t)(gy*PW + gx)*64 + f4*8);
        *reinterpret_cast<float4*>(smh + b2*ITH + pos*72 + f4*8) = v;
    }

    const uint32_t itb = smb + (uint32_t)bw*ITH*2;

    float acc[4][8][4];
#pragma unroll
    for (int mi = 0; mi < 4; ++mi)
#pragma unroll
        for (int nj = 0; nj < 8; ++nj)
#pragma unroll
            for (int r = 0; r < 4; ++r) acc[mi][nj][r] = 0.f;

    for (int t = 0; t < 162; ++t) {
        if (t == 161) asm volatile("cp.async.wait_group 0;" ::: "memory");
        else          asm volatile("cp.async.wait_group 1;" ::: "memory");
        __syncthreads();
        if (t + 2 < 162) {
            stageB(t+2, (t+2) % 3);
            asm volatile("cp.async.commit_group;" ::: "memory");
        }

        const int kk = t >> 1, ci0 = (t & 1) * 32;
        const int ky = kk / 9, kx = kk - ky*9;
        const uint32_t bB = smemB + (uint32_t)(t % 3)*(64*40*2);

#pragma unroll
        for (int ks = 0; ks < 2; ++ks) {
            const int kh0 = ci0 + ks*16;
            uint32_t a[4][4];
#pragma unroll
            for (int mi = 0; mi < 4; ++mi)
                ldsm4(a[mi], itb + 2u*(uint32_t)(((my0 + mi + ky)*24 + kx)*72 + kh0) + laneA);
#pragma unroll
            for (int nj2 = 0; nj2 < 4; ++nj2) {
                uint32_t b[4];
                ldsm4(b, bB + 2u*(uint32_t)((nj2*16)*40 + ks*16) + laneB);
#pragma unroll
                for (int mi = 0; mi < 4; ++mi) {
                    mma16(acc[mi][2*nj2],   a[mi], b[0], b[1]);
                    mma16(acc[mi][2*nj2+1], a[mi], b[2], b[3]);
                }
            }
        }
    }

    const int n = n0 + bw;
#pragma unroll
    for (int mi = 0; mi < 4; ++mi) {
        int y = y0 + my0 + mi;
        if (y >= 40) continue;
#pragma unroll
        for (int nj = 0; nj < 8; ++nj)
#pragma unroll
            for (int r = 0; r < 4; ++r) {
                int x = x0 + gid + ((r >> 1) << 3);
                if (x < 40) {
                    int nc = nj*8 + tig*2 + (r & 1);
                    float* outp = (nc < 32) ? g_k : g_v;
                    int cg = nc & 31;
                    outp[((size_t)(n*CCH + g*32 + cg)*40 + y)*40 + x] = acc[mi][nj][r];
                }
            }
    }
}

// ---------------- 3: attention (mma, pipelined) + fused gates ---------------
#define LSP  1604            // logits row stride
#define CHW  320             // staged K/V chunk width
#define CHP  324             // chunk row stride
// ls + qs + 3 kv buffers; os & gate weights alias kv
#define ATTN_SMEM ((16*LSP + 16*36 + 3*32*CHP) * 4)   // 229376

__global__ __launch_bounds__(256)
void attn_kernel(const float* __restrict__ tau,
                 const float* __restrict__ Wa_i, const float* __restrict__ Wa_f,
                 const float* __restrict__ Wa_g, const float* __restrict__ Wa_o,
                 const float* __restrict__ b_i,  const float* __restrict__ b_f,
                 const float* __restrict__ b_g,  const float* __restrict__ b_o,
                 const float* __restrict__ c_prev, float* __restrict__ outp)
{
    extern __shared__ float smf[];
    float* ls  = smf;                 // [16][LSP]
    float* qs  = ls + 16*LSP;         // [16][36]   (reused as oq later)
    float* kvb = qs + 16*36;          // 3 x [32][CHP]

    int bz = blockIdx.x;
    int qt = bz % 144;
    int g  = (bz / 144) & 7;
    int n  = bz / 1152;
    int q0 = qt * 16;

    const float* qb = g_q + ((size_t)(n*CCH) + g*32)*HWQ + q0;
    const float* kb = g_k + ((size_t)(n*CCH) + g*32)*DD;
    const float* vb = g_v + ((size_t)(n*CCH) + g*32)*DD;
    int tid = threadIdx.x;
    int wid = tid >> 5, lane = tid & 31;
    int gid = lane >> 2, tig = lane & 3;
    uint32_t kvaddr = smem_u32(kvb);

    auto stage = [&](int c, int buf) {
        const float* src = ((c < 5) ? kb : vb) + (c % 5)*CHW;
        uint32_t bbase = kvaddr + (uint32_t)buf*(32*CHP*4);
        for (int u = tid; u < 32*80; u += 256) {
            int cc = u / 80, seg = u - cc*80;
            cp16(bbase + (uint32_t)(cc*CHP + seg*4)*4, src + (size_t)cc*DD + seg*4);
        }
    };

    stage(0, 0);
    asm volatile("cp.async.commit_group;" ::: "memory");
    stage(1, 1);
    asm volatile("cp.async.commit_group;" ::: "memory");

    for (int idx = tid; idx < 512; idx += 256) {
        int qi = idx >> 5, c = idx & 31;
        qs[qi*36 + c] = qb[c*HWQ + qi];
    }
    float tg = tau[g];

    float acc2[4][4];
#pragma unroll
    for (int nj = 0; nj < 4; ++nj)
#pragma unroll
        for (int r = 0; r < 4; ++r) acc2[nj][r] = 0.f;

    for (int ch = 0; ch < 10; ++ch) {
        if (ch == 9) asm volatile("cp.async.wait_group 0;" ::: "memory");
        else         asm volatile("cp.async.wait_group 1;" ::: "memory");
        __syncthreads();
        if (ch + 2 < 10) {
            stage(ch+2, (ch+2) % 3);
            asm volatile("cp.async.commit_group;" ::: "memory");
        }

        const float* kv = kvb + (ch % 3)*(32*CHP);

        if (ch < 5) {
            // ---- phase 1: logits for chunk ch ----
            int d0 = ch*CHW;
            int nw = wid*40;
            float acc[5][4];
#pragma unroll
            for (int nj = 0; nj < 5; ++nj)
#pragma unroll
                for (int r = 0; r < 4; ++r) acc[nj][r] = 0.f;

#pragma unroll
            for (int ks = 0; ks < 4; ++ks) {
                int kbi = ks*8;
                uint32_t a[4];
                a[0] = __float_as_uint(qs[gid*36     + kbi + tig]);
                a[1] = __float_as_uint(qs[(gid+8)*36 + kbi + tig]);
                a[2] = __float_as_uint(qs[gid*36     + kbi + tig + 4]);
                a[3] = __float_as_uint(qs[(gid+8)*36 + kbi + tig + 4]);
#pragma unroll
                for (int nj = 0; nj < 5; ++nj) {
                    uint32_t b0 = __float_as_uint(kv[(kbi+tig)*CHP   + nw + nj*8 + gid]);
                    uint32_t b1 = __float_as_uint(kv[(kbi+tig+4)*CHP + nw + nj*8 + gid]);
                    mma8(acc[nj], a, b0, b1);
                }
            }
#pragma unroll
            for (int nj = 0; nj < 5; ++nj) {
                int d = d0 + nw + nj*8 + 2*tig;
                float2 lo = make_float2(acc[nj][0]*tg, acc[nj][1]*tg);
                float2 hi = make_float2(acc[nj][2]*tg, acc[nj][3]*tg);
                *reinterpret_cast<float2*>(ls + gid*LSP     + d) = lo;
                *reinterpret_cast<float2*>(ls + (gid+8)*LSP + d) = hi;
            }
        } else {
            if (ch == 5) {
                // ---- softmax (all logits ready; V staging in flight) ----
                for (int q = wid; q < 16; q += 8) {
                    float* row = ls + q*LSP;
                    float m = -1e30f;
                    for (int d = lane; d < DD; d += 32) m = fmaxf(m, row[d]);
#pragma unroll
                    for (int off = 16; off; off >>= 1) m = fmaxf(m, __shfl_xor_sync(~0u, m, off));
                    float s = 0.f;
                    for (int d = lane; d < DD; d += 32) { float e = fastexp(row[d]-m); row[d] = e; s += e; }
#pragma unroll
                    for (int off = 16; off; off >>= 1) s += __shfl_xor_sync(~0u, s, off);
                    float inv = 1.f / s;
                    for (int d = lane; d < DD; d += 32) row[d] *= inv;
                }
                __syncthreads();
            }
            // ---- phase 2: O partial for V chunk (ch-5) ----
            int d0 = (ch-5)*CHW;
#pragma unroll
            for (int ks = 0; ks < 5; ++ks) {
                int kl = wid*40 + ks*8;
                uint32_t a[4];
                a[0] = __float_as_uint(ls[gid*LSP     + d0 + kl + tig]);
                a[1] = __float_as_uint(ls[(gid+8)*LSP + d0 + kl + tig]);
                a[2] = __float_as_uint(ls[gid*LSP     + d0 + kl + tig + 4]);
                a[3] = __float_as_uint(ls[(gid+8)*LSP + d0 + kl + tig + 4]);
#pragma unroll
                for (int nj = 0; nj < 4; ++nj) {
                    uint32_t b0 = __float_as_uint(kv[(nj*8+gid)*CHP + kl + tig]);
                    uint32_t b1 = __float_as_uint(kv[(nj*8+gid)*CHP + kl + tig + 4]);
                    mma8(acc2[nj], a, b0, b1);
                }
            }
        }
    }
    __syncthreads();   // all mma done; kv region free for reuse

    // os aliases kv buffers
    float* os  = kvb;              // [8][16][33] = 4224 floats
    float* wsm = kvb + 4352;       // 4*1024
    float* bsm = wsm + 4096;       // 4*32

#pragma unroll
    for (int nj = 0; nj < 4; ++nj)
#pragma unroll
        for (int r = 0; r < 4; ++r) {
            int q = gid + ((r >> 1) << 3);
            int c = nj*8 + tig*2 + (r & 1);
            os[(wid*16 + q)*33 + c] = acc2[nj][r];
        }
    // gate weights/biases
    for (int u = tid; u < 1024; u += 256) {
        int e = u >> 8, off = (u & 255)*4;
        const float* Wa = (e==0)?Wa_i:(e==1)?Wa_f:(e==2)?Wa_g:Wa_o;
        *reinterpret_cast<float4*>(wsm + e*1024 + off) =
            *reinterpret_cast<const float4*>(Wa + (size_t)g*1024 + off);
    }
    if (tid < 128) {
        int e = tid >> 5, c = tid & 31;
        const float* bb = (e==0)?b_i:(e==1)?b_f:(e==2)?b_g:b_o;
        bsm[tid] = bb[g*32 + c];
    }
    __syncthreads();

    // reduce partials into oq (reuse qs)
    float* oq = qs;
    for (int u = tid; u < 512; u += 256) {
        int q = u >> 5, c = u & 31;
        float s = 0.f;
#pragma unroll
        for (int w = 0; w < 8; ++w) s += os[(w*16 + q)*33 + c];
        oq[q*33 + c] = s;
    }
    __syncthreads();

    // fused gates + cell update
    for (int u = tid; u < 512; u += 256) {
        int q = u & 15, c = u >> 4;
        float a0 = bsm[c], a1 = bsm[32+c], a2 = bsm[64+c], a3 = bsm[96+c];
#pragma unroll 8
        for (int cc = 0; cc < 32; ++cc) {
            float o = oq[q*33 + cc];
            a0 = fmaf(wsm[        c*32 + cc], o, a0);
            a1 = fmaf(wsm[1024 + c*32 + cc], o, a1);
            a2 = fmaf(wsm[2048 + c*32 + cc], o, a2);
            a3 = fmaf(wsm[3072 + c*32 + cc], o, a3);
        }
        size_t off = ((size_t)(n*CCH) + g*32 + c)*HWQ + q0 + q;
        float gi = sigm (a0 + g_gp[0][off]);
        float gf = sigm (a1 + g_gp[1][off]);
        float gg = ftanh(a2 + g_gp[2][off]);
        float go = sigm (a3 + g_gp[3][off]);
        float cn = gf * c_prev[off] + gi * gg;
        outp[off] = go * ftanh(cn);
    }
}

// ---------------- launch ----------------------------------------------------
extern "C" void kernel_launch(void* const* d_in, const int* in_sizes, int n_in,
                              void* d_out, int out_size)
{
    (void)in_sizes; (void)n_in; (void)out_size;
    const float* inp    = (const float*)d_in[0];
    const float* h_prev = (const float*)d_in[1];
    const float* c_prev = (const float*)d_in[2];
    const float* Wx     = (const float*)d_in[3];
    const float* Wxg    = (const float*)d_in[4];
    const float* tau    = (const float*)d_in[5];
    const float* Wq     = (const float*)d_in[6];
    const float* Wk     = (const float*)d_in[7];
    const float* Wv     = (const float*)d_in[8];
    const float* Wa_i   = (const float*)d_in[9];
    const float* Wxh_i  = (const float*)d_in[10];
    const float* b_i    = (const float*)d_in[11];
    const float* Wa_f   = (const float*)d_in[12];
    const float* Wxh_f  = (const float*)d_in[13];
    const float* b_f    = (const float*)d_in[14];
    const float* Wa_g   = (const float*)d_in[15];
    const float* Wxh_g  = (const float*)d_in[16];
    const float* b_g    = (const float*)d_in[17];
    const float* Wa_o   = (const float*)d_in[18];
    const float* Wxh_o  = (const float*)d_in[19];
    const float* b_o    = (const float*)d_in[20];
    float* out = (float*)d_out;

    cudaFuncSetAttribute(attn_kernel,
                         cudaFuncAttributeMaxDynamicSharedMemorySize, ATTN_SMEM);
    cudaFuncSetAttribute(conv_same_kernel,
                         cudaFuncAttributeMaxDynamicSharedMemorySize, SMEM_S);
    cudaFuncSetAttribute(conv_valid_kernel,
                         cudaFuncAttributeMaxDynamicSharedMemorySize, SMEM_V);

    zero_xh2_kernel<<<2048, 256>>>();
    wtrans_kernel<<<GG*224, 256>>>(Wq, Wxh_i, Wxh_f, Wxh_g, Wxh_o, Wk, Wv);
    proj_kernel<<<dim3(9, 32, 4), 256>>>(inp, h_prev, Wx, Wxg);
    conv_same_kernel<<<dim3(9, 8, 4), 256, SMEM_S>>>();
    conv_valid_kernel<<<dim3(9, 8, 2), 256, SMEM_V>>>();
    attn_kernel<<<NN*GG*144, 256, ATTN_SMEM>>>(tau, Wa_i, Wa_f, Wa_g, Wa_o,
                                               b_i, b_f, b_g, b_o, c_prev, out);
}

// round 16
// speedup vs baseline: 1.0562x; 1.0542x over previous
#include <cuda_runtime.h>
#include <cuda_fp16.h>
#include <cstdint>
#include <math.h>

// Problem constants
#define NN   4
#define II   64
#define CCH  256
#define GG   8
#define CG   32
#define KS   9
#define HH   48
#define HWQ  (48*48)   // 2304
#define HD   40
#define DD   (40*40)   // 1600
#define PW   56
#define PHW  (56*56)

// ---------------- scratch (device globals; no allocation allowed) -----------
__device__ __align__(128) __half g_xh2[NN*GG*PHW*64];
__device__ __align__(128) __half g_wS[GG*81*160*64];
__device__ __align__(128) __half g_wV[GG*81*64*64];
__device__ __align__(128) __half g_q16[NN*CCH*HWQ];       // [n][c][q]
__device__ __align__(128) __half g_k16[NN*GG*DD*32];      // [n][g][d][c]
__device__ __align__(128) __half g_v16[NN*CCH*DD];        // [n][c][d]
__device__ __align__(128) float g_gp[4][NN*CCH*HWQ];

// FFMA-only exp for softmax
__device__ __forceinline__ float fastexp(float x) {
    float z = fmaxf(x * 1.4426950408889634f, -120.f);
    float t = z + 12582912.f;
    int   e = __float_as_int(t) - 0x4B400000;
    float f = z - (t - 12582912.f);
    float p = fmaf(f, 0.0013333558f, 0.0096181291f);
    p = fmaf(f, p, 0.0555041087f);
    p = fmaf(f, p, 0.2402265069f);
    p = fmaf(f, p, 0.69314718056f);
    p = fmaf(f, p, 1.0f);
    return __int_as_float(__float_as_int(p) + (e << 23));
}
__device__ __forceinline__ float ftanh(float x) {
    float t; asm("tanh.approx.f32 %0, %1;" : "=f"(t) : "f"(x)); return t;
}
__device__ __forceinline__ float sigm(float x) {
    return fmaf(ftanh(x * 0.5f), 0.5f, 0.5f);
}

// m16n8k16 fp16 mma.sync with fp32 accumulate
__device__ __forceinline__ void mma16(float* c, const uint32_t* a,
                                      uint32_t b0, uint32_t b1) {
    asm volatile(
        "mma.sync.aligned.m16n8k16.row.col.f32.f16.f16.f32 "
        "{%0,%1,%2,%3}, {%4,%5,%6,%7}, {%8,%9}, {%0,%1,%2,%3};"
        : "+f"(c[0]), "+f"(c[1]), "+f"(c[2]), "+f"(c[3])
        : "r"(a[0]), "r"(a[1]), "r"(a[2]), "r"(a[3]), "r"(b0), "r"(b1));
}
__device__ __forceinline__ void ldsm4(uint32_t* r, uint32_t addr) {
    asm volatile("ldmatrix.sync.aligned.m8n8.x4.shared.b16 {%0,%1,%2,%3}, [%4];"
        : "=r"(r[0]), "=r"(r[1]), "=r"(r[2]), "=r"(r[3]) : "r"(addr));
}
__device__ __forceinline__ void ldsm2(uint32_t* r, uint32_t addr) {
    asm volatile("ldmatrix.sync.aligned.m8n8.x2.shared.b16 {%0,%1}, [%2];"
        : "=r"(r[0]), "=r"(r[1]) : "r"(addr));
}
__device__ __forceinline__ void cp16(uint32_t dst, const void* src) {
    asm volatile("cp.async.cg.shared.global [%0], [%1], 16;" :: "r"(dst), "l"(src));
}
__device__ __forceinline__ uint32_t smem_u32(const void* p) {
    uint32_t a;
    asm("{ .reg .u64 t; cvta.to.shared.u64 t, %1; cvt.u32.u64 %0, t; }" : "=r"(a) : "l"(p));
    return a;
}

// ---------------- 0: zero padded xh buffer ----------------------------------
__global__ void zero_xh2_kernel() {
    size_t total16 = (size_t)NN*GG*PHW*64*2/16;
    uint4* p = reinterpret_cast<uint4*>(g_xh2);
    for (size_t i = (size_t)blockIdx.x*blockDim.x + threadIdx.x; i < total16;
         i += (size_t)gridDim.x*blockDim.x)
        p[i] = make_uint4(0u,0u,0u,0u);
}

// ---------------- 0b: weight transpose via smem tile (coalesced, fp16) ------
__global__ __launch_bounds__(256)
void wtrans_kernel(const float* __restrict__ Wq, const float* __restrict__ Wi,
                   const float* __restrict__ Wf, const float* __restrict__ Wg,
                   const float* __restrict__ Wo, const float* __restrict__ Wk,
                   const float* __restrict__ Wv)
{
    __shared__ float sm[5184];
    int b = blockIdx.x;          // 0..1791
    int g = b / 224;
    int r = b % 224;
    int tid = threadIdx.x;

    const float* W;
    __half* dst;
    int row, NCr, rr;
    if (r < 160) {
        int j = r >> 5;
        W = (j==0)?Wq:(j==1)?Wi:(j==2)?Wf:(j==3)?Wg:Wo;
        row = r & 31; dst = g_wS; NCr = 160; rr = r;
    } else {
        int r2 = r - 160;
        W = (r2 < 32) ? Wk : Wv;
        row = r2 & 31; dst = g_wV; NCr = 64; rr = r2;
    }
    const float* src = W + (size_t)(g*32 + row)*5184;
    for (int u = tid; u < 5184; u += 256) sm[u] = src[u];
    __syncthreads();
    for (int u = tid; u < 5184; u += 256) {
        int k = u >> 6, ci = u & 63;
        dst[((size_t)(g*81 + k)*NCr + rr)*64 + ci] = __float2half_rn(sm[ci*81 + k]);
    }
}

// ---------------- 1: projection + build padded channel-last xh (fp16) -------
__global__ __launch_bounds__(256)
void proj_kernel(const float* __restrict__ inp, const float* __restrict__ h,
                 const float* __restrict__ Wx, const float* __restrict__ Wxg)
{
    __shared__ float ws[8*320];
    int n  = blockIdx.z;
    int c0 = blockIdx.y * 8;
    int p0 = blockIdx.x * 256;
    int tid = threadIdx.x;

    for (int idx = tid; idx < 8*320; idx += 256) {
        int j = idx / 320, ic = idx - j*320;
        ws[idx] = (ic < 64) ? Wx[(c0+j)*64 + ic] : Wxg[(c0+j)*256 + (ic-64)];
    }
    __syncthreads();

    int p = p0 + tid;
    float acc[8];
#pragma unroll
    for (int j = 0; j < 8; ++j) acc[j] = 0.f;

    const float* ib = inp + (size_t)n*II*HWQ + p;
    const float* hb = h   + (size_t)n*CCH*HWQ + p;

#pragma unroll 4
    for (int ic = 0; ic < 64; ++ic) {
        float v = ib[ic*HWQ];
#pragma unroll
        for (int j = 0; j < 8; ++j) acc[j] = fmaf(ws[j*320+ic], v, acc[j]);
    }
#pragma unroll 4
    for (int ic = 0; ic < 256; ++ic) {
        float v = hb[ic*HWQ];
#pragma unroll
        for (int j = 0; j < 8; ++j) acc[j] = fmaf(ws[j*320+64+ic], v, acc[j]);
    }

    int y = p / 48, x = p - y*48;
    int g = c0 >> 5;
    __half* xb = g_xh2 + ((size_t)(n*GG + g)*PHW + (y+4)*PW + (x+4))*64;
#pragma unroll
    for (int j = 0; j < 8; ++j) {
        int cg = (c0 + j) & 31;
        xb[cg]      = __float2half_rn(acc[j]);
        xb[32 + cg] = __float2half_rn(hb[(c0+j)*HWQ]);
    }
}

// ---------------- 2a: SAME grouped conv (q + 4 gates), fp16 mma + ldmatrix --
#define ITH (24*24*72)
#define SMEM_S (ITH*2 + 3*160*40*2)   // 121344
__global__ __launch_bounds__(256, 1)
void conv_same_kernel()
{
    extern __shared__ __half smh[];
    __half* IT = smh;

    const int tid = threadIdx.x;
    const int wid = tid >> 5, lane = tid & 31;
    const int gid = lane >> 2, tig = lane & 3;
    const int my0 = (wid >> 1) * 4;
    const int nb  = (wid & 1) * 80;

    const int g  = blockIdx.y;
    const int n  = blockIdx.z;
    const int x0 = (blockIdx.x % 3) * 16;
    const int y0 = (blockIdx.x / 3) * 16;

    float* outs[5] = {nullptr, g_gp[0], g_gp[1], g_gp[2], g_gp[3]};

    const __half* xsrc = g_xh2 + (size_t)(n*GG + g)*PHW*64;
    const __half* wg   = g_wS + (size_t)g*81*160*64;
    const uint32_t itb   = smem_u32(smh);
    const uint32_t smemB = itb + ITH*2;

    const uint32_t laneA = 2u * ((((lane >> 3) & 1)*8 + (lane & 7))*72 + (lane >> 4)*8);
    const uint32_t laneB = 2u * ((((lane >> 4) & 1)*8 + (lane & 7))*40 + ((lane >> 3) & 1)*8);

    auto stageB = [&](int t, int buf) {
        int kk = t >> 1, ci0 = (t & 1) * 32;
        const __half* wsrc = wg + (size_t)kk*160*64 + ci0;
        uint32_t bbase = smemB + (uint32_t)buf*(160*40*2);
        for (int u = tid; u < 160*4; u += 256) {
            int n2 = u >> 2, seg = u & 3;
            cp16(bbase + (uint32_t)(n2*80 + seg*16), wsrc + n2*64 + seg*8);
        }
    };

    stageB(0, 0);
    asm volatile("cp.async.commit_group;" ::: "memory");
    stageB(1, 1);
    asm volatile("cp.async.commit_group;" ::: "memory");

    for (int u = tid; u < 24*24*8; u += 256) {
        int f4 = u & 7, pos = u >> 3;
        int yy = pos / 24, xx = pos - yy*24;
        int gy = min(y0 + yy, 55), gx = min(x0 + xx, 55);
        float4 v = *reinterpret_cast<const float4*>(xsrc + (size_t)(gy*PW + gx)*64 + f4*8);
        *reinterpret_cast<float4*>(IT + pos*72 + f4*8) = v;
    }

    float acc[4][10][4];
#pragma unroll
    for (int mi = 0; mi < 4; ++mi)
#pragma unroll
        for (int nj = 0; nj < 10; ++nj)
#pragma unroll
            for (int r = 0; r < 4; ++r) acc[mi][nj][r] = 0.f;

    for (int t = 0; t < 162; ++t) {
        if (t == 161) asm volatile("cp.async.wait_group 0;" ::: "memory");
        else          asm volatile("cp.async.wait_group 1;" ::: "memory");
        __syncthreads();
        if (t + 2 < 162) {
            stageB(t+2, (t+2) % 3);
            asm volatile("cp.async.commit_group;" ::: "memory");
        }

        const int kk = t >> 1, ci0 = (t & 1) * 32;
        const int ky = kk / 9, kx = kk - ky*9;
        const uint32_t bB = smemB + (uint32_t)(t % 3)*(160*40*2);

#pragma unroll
        for (int ks = 0; ks < 2; ++ks) {
            const int kh0 = ci0 + ks*16;
            uint32_t a[4][4];
#pragma unroll
            for (int mi = 0; mi < 4; ++mi)
                ldsm4(a[mi], itb + 2u*(uint32_t)(((my0 + mi + ky)*24 + kx)*72 + kh0) + laneA);
#pragma unroll
            for (int nj2 = 0; nj2 < 5; ++nj2) {
                uint32_t b[4];
                ldsm4(b, bB + 2u*(uint32_t)((nb + nj2*16)*40 + ks*16) + laneB);
#pragma unroll
                for (int mi = 0; mi < 4; ++mi) {
                    mma16(acc[mi][2*nj2],   a[mi], b[0], b[1]);
                    mma16(acc[mi][2*nj2+1], a[mi], b[2], b[3]);
                }
            }
        }
    }

#pragma unroll
    for (int mi = 0; mi < 4; ++mi) {
        int y = y0 + my0 + mi;
#pragma unroll
        for (int nj = 0; nj < 10; ++nj)
#pragma unroll
            for (int r = 0; r < 4; ++r) {
                int x = x0 + gid + ((r >> 1) << 3);
                int nc = nb + nj*8 + tig*2 + (r & 1);
                int conv = nc >> 5, cg = nc & 31;
                if (conv == 0)
                    g_q16[((size_t)(n*CCH + g*32 + cg)*48 + y)*48 + x] =
                        __float2half_rn(acc[mi][nj][r]);
                else
                    outs[conv][((size_t)(n*CCH + g*32 + cg)*48 + y)*48 + x] = acc[mi][nj][r];
            }
    }
}

// ---------------- 2b: VALID grouped conv (k, v), fp16, CK=64 (81 iters) -----
#define SMEM_V (2*ITH*2 + 3*64*72*2)  // 193536
__global__ __launch_bounds__(256, 1)
void conv_valid_kernel()
{
    extern __shared__ __half smh[];

    const int tid = threadIdx.x;
    const int wid = tid >> 5, lane = tid & 31;
    const int gid = lane >> 2, tig = lane & 3;
    const int bw  = wid >> 2;
    const int my0 = (wid & 3) * 4;

    const int g  = blockIdx.y;
    const int n0 = blockIdx.z * 2;
    const int x0 = (blockIdx.x % 3) * 16;
    const int y0 = (blockIdx.x / 3) * 16;

    const __half* wg = g_wV + (size_t)g*81*64*64;
    const uint32_t smb   = smem_u32(smh);
    const uint32_t smemB = smb + 2*ITH*2;

    const uint32_t laneA  = 2u * ((((lane >> 3) & 1)*8 + (lane & 7))*72 + (lane >> 4)*8);
    const uint32_t laneB7 = 2u * ((((lane >> 4) & 1)*8 + (lane & 7))*72 + ((lane >> 3) & 1)*8);

    auto stageB = [&](int t, int buf) {
        const __half* wsrc = wg + (size_t)t*64*64;
        uint32_t bbase = smemB + (uint32_t)buf*(64*72*2);
        for (int u = tid; u < 64*8; u += 256) {
            int n2 = u >> 3, seg = u & 7;
            cp16(bbase + (uint32_t)(n2*144 + seg*16), wsrc + n2*64 + seg*8);
        }
    };

    stageB(0, 0);
    asm volatile("cp.async.commit_group;" ::: "memory");
    stageB(1, 1);
    asm volatile("cp.async.commit_group;" ::: "memory");

    for (int u = tid; u < 2*24*24*8; u += 256) {
        int b2 = u / (24*24*8);
        int u2 = u - b2*(24*24*8);
        int f4 = u2 & 7, pos = u2 >> 3;
        int yy = pos / 24, xx = pos - yy*24;
        int gy = min(y0 + 4 + yy, 55), gx = min(x0 + 4 + xx, 55);
        const __half* xsrc = g_xh2 + (size_t)((n0+b2)*GG + g)*PHW*64;
        float4 v = *reinterpret_cast<const float4*>(xsrc + (size_t)(gy*PW + gx)*64 + f4*8);
        *reinterpret_cast<float4*>(smh + b2*ITH + pos*72 + f4*8) = v;
    }

    const uint32_t itb = smb + (uint32_t)bw*ITH*2;

    float acc[4][8][4];
#pragma unroll
    for (int mi = 0; mi < 4; ++mi)
#pragma unroll
        for (int nj = 0; nj < 8; ++nj)
#pragma unroll
            for (int r = 0; r < 4; ++r) acc[mi][nj][r] = 0.f;

    for (int t = 0; t < 81; ++t) {
        if (t == 80) asm volatile("cp.async.wait_group 0;" ::: "memory");
        else         asm volatile("cp.async.wait_group 1;" ::: "memory");
        __syncthreads();
        if (t + 2 < 81) {
            stageB(t+2, (t+2) % 3);
            asm volatile("cp.async.commit_group;" ::: "memory");
        }

        const int ky = t / 9, kx = t - ky*9;
        const uint32_t bB = smemB + (uint32_t)(t % 3)*(64*72*2);

#pragma unroll
        for (int ks = 0; ks < 4; ++ks) {
            const int kh0 = ks*16;
            uint32_t a[4][4];
#pragma unroll
            for (int mi = 0; mi < 4; ++mi)
                ldsm4(a[mi], itb + 2u*(uint32_t)(((my0 + mi + ky)*24 + kx)*72 + kh0) + laneA);
#pragma unroll
            for (int nj2 = 0; nj2 < 4; ++nj2) {
                uint32_t b[4];
                ldsm4(b, bB + 2u*(uint32_t)((nj2*16)*72 + ks*16) + laneB7);
#pragma unroll
                for (int mi = 0; mi < 4; ++mi) {
                    mma16(acc[mi][2*nj2],   a[mi], b[0], b[1]);
                    mma16(acc[mi][2*nj2+1], a[mi], b[2], b[3]);
                }
            }
        }
    }

    const int n = n0 + bw;
#pragma unroll
    for (int mi = 0; mi < 4; ++mi) {
        int y = y0 + my0 + mi;
        if (y >= 40) continue;
#pragma unroll
        for (int nj = 0; nj < 8; ++nj)
#pragma unroll
            for (int r = 0; r < 4; ++r) {
                int x = x0 + gid + ((r >> 1) << 3);
                if (x < 40) {
                    int nc = nj*8 + tig*2 + (r & 1);
                    int cg = nc & 31;
                    int d = y*40 + x;
                    if (nc < 32)   // k -> [n][g][d][c]
                        g_k16[((size_t)(n*GG + g)*DD + d)*32 + cg] =
                            __float2half_rn(acc[mi][nj][r]);
                    else           // v -> [n][c][d]
                        g_v16[((size_t)(n*CCH) + g*32 + cg)*DD + d] =
                            __float2half_rn(acc[mi][nj][r]);
                }
            }
    }
}

// ---------------- 3: attention fp16 mma + fused gates ------------------------
#define LSP   1604                 // fp32 logits stride (floats)
#define PSTR  1608                 // fp16 P stride (halves)
#define KVBUF 25600                // bytes per kv buffer (K: 320x40x2)
#define LS_BYTES   (16*LSP*4)      // 102656
#define P_OFF      LS_BYTES
#define QS_OFF     (P_OFF + 16*PSTR*2)      // 154112
#define KV_OFF     (QS_OFF + 16*40*2)       // 155392
#define ATTN_SMEM  (KV_OFF + 2*KVBUF)       // 206592

__global__ __launch_bounds__(256)
void attn_kernel(const float* __restrict__ tau,
                 const float* __restrict__ Wa_i, const float* __restrict__ Wa_f,
                 const float* __restrict__ Wa_g, const float* __restrict__ Wa_o,
                 const float* __restrict__ b_i,  const float* __restrict__ b_f,
                 const float* __restrict__ b_g,  const float* __restrict__ b_o,
                 const float* __restrict__ c_prev, float* __restrict__ outp)
{
    extern __shared__ float smf[];
    float*  ls = smf;                                        // [16][LSP] fp32
    __half* Pp = (__half*)((char*)smf + P_OFF);              // [16][PSTR] fp16
    __half* qs = (__half*)((char*)smf + QS_OFF);             // [16][40] fp16

    int bz = blockIdx.x;
    int qt = bz % 144;
    int g  = (bz / 144) & 7;
    int n  = bz / 1152;
    int q0 = qt * 16;

    const __half* qb = g_q16 + ((size_t)(n*CCH) + g*32)*HWQ + q0;
    const __half* kb = g_k16 + (size_t)(n*GG + g)*DD*32;
    const __half* vb = g_v16 + ((size_t)(n*CCH) + g*32)*DD;
    int tid = threadIdx.x;
    int wid = tid >> 5, lane = tid & 31;
    int gid = lane >> 2, tig = lane & 3;

    const uint32_t smb    = smem_u32(smf);
    const uint32_t Pb     = smb + P_OFF;
    const uint32_t qsb    = smb + QS_OFF;
    const uint32_t kvbase = smb + KV_OFF;

    // ldmatrix lane offsets
    const uint32_t laneAq = 2u*((((lane>>3)&1)*8 + (lane&7))*40   + (lane>>4)*8);
    const uint32_t laneAp = 2u*((((lane>>3)&1)*8 + (lane&7))*1608 + (lane>>4)*8);
    const uint32_t laneBk = 2u*((((lane>>4)&1)*8 + (lane&7))*40   + ((lane>>3)&1)*8);
    const int      l15    = lane & 15;
    const uint32_t laneBk2= 2u*((l15&7)*40  + ((l15>>3)&1)*8);
    const uint32_t laneBv2= 2u*((l15&7)*328 + ((l15>>3)&1)*8);

    auto stage = [&](int c, int buf) {
        uint32_t bbase = kvbase + (uint32_t)buf*KVBUF;
        if (c < 5) {      // K chunk -> [320 d][40 c]
            const __half* src = kb + (size_t)(c*320)*32;
            for (int u = tid; u < 1280; u += 256) {
                int dd = u >> 2, seg = u & 3;
                cp16(bbase + (uint32_t)(dd*80 + seg*16), src + dd*32 + seg*8);
            }
        } else {          // V chunk -> [32 c][328 d]
            const __half* src = vb + (c-5)*320;
            for (int u = tid; u < 1280; u += 256) {
                int cc = u / 40, seg = u % 40;
                cp16(bbase + (uint32_t)(cc*656 + seg*16), src + (size_t)cc*DD + seg*8);
            }
        }
    };

    stage(0, 0);
    asm volatile("cp.async.commit_group;" ::: "memory");
    stage(1, 1);
    asm volatile("cp.async.commit_group;" ::: "memory");

    // load Q [16 q][32 c] fp16
    for (int idx = tid; idx < 512; idx += 256) {
        int qi = idx >> 5, c = idx & 31;
        qs[qi*40 + c] = qb[c*HWQ + qi];
    }
    float tg = tau[g];

    uint32_t aq[2][4];
    float acc2[4];
#pragma unroll
    for (int r = 0; r < 4; ++r) acc2[r] = 0.f;

    const int ntile = wid & 3, khalf = wid >> 2;

    for (int ch = 0; ch < 10; ++ch) {
        if (ch == 9) asm volatile("cp.async.wait_group 0;" ::: "memory");
        else         asm volatile("cp.async.wait_group 1;" ::: "memory");
        __syncthreads();

        uint32_t kvB = kvbase + (uint32_t)(ch & 1)*KVBUF;

        if (ch == 0) {      // Q fragments (held across phase 1)
            ldsm4(aq[0], qsb + laneAq);
            ldsm4(aq[1], qsb + 32 + laneAq);
        }

        if (ch < 5) {
            // ---- phase 1: S chunk = Q K^T ----
            int d0 = ch*320;
            int nw = wid*40;
            float acc[5][4];
#pragma unroll
            for (int nj = 0; nj < 5; ++nj)
#pragma unroll
                for (int r = 0; r < 4; ++r) acc[nj][r] = 0.f;

#pragma unroll
            for (int gt = 0; gt < 2; ++gt) {
                uint32_t b0[4], b1[4];
                uint32_t base = kvB + (uint32_t)(nw + gt*16)*80;
                ldsm4(b0, base + laneBk);        // k cols 0-15
                ldsm4(b1, base + 32 + laneBk);   // k cols 16-31
                mma16(acc[gt*2],   aq[0], b0[0], b0[1]);
                mma16(acc[gt*2],   aq[1], b1[0], b1[1]);
                mma16(acc[gt*2+1], aq[0], b0[2], b0[3]);
                mma16(acc[gt*2+1], aq[1], b1[2], b1[3]);
            }
            {   // last 8 d rows
                uint32_t b0[2], b1[2];
                uint32_t base = kvB + (uint32_t)(nw + 32)*80;
                ldsm2(b0, base + laneBk2);
                ldsm2(b1, base + 32 + laneBk2);
                mma16(acc[4], aq[0], b0[0], b0[1]);
                mma16(acc[4], aq[1], b1[0], b1[1]);
            }
#pragma unroll
            for (int nj = 0; nj < 5; ++nj) {
                int d = d0 + nw + nj*8 + 2*tig;
                float2 lo = make_float2(acc[nj][0]*tg, acc[nj][1]*tg);
                float2 hi = make_float2(acc[nj][2]*tg, acc[nj][3]*tg);
                *reinterpret_cast<float2*>(ls + gid*LSP     + d) = lo;
                *reinterpret_cast<float2*>(ls + (gid+8)*LSP + d) = hi;
            }
        } else {
            if (ch == 5) {
                // ---- softmax: fp32 logits -> fp16 P ----
                for (int q = wid; q < 16; q += 8) {
                    float* row = ls + q*LSP;
                    __half* prow = Pp + q*PSTR;
                    float m = -1e30f;
                    for (int d = lane; d < DD; d += 32) m = fmaxf(m, row[d]);
#pragma unroll
                    for (int off = 16; off; off >>= 1) m = fmaxf(m, __shfl_xor_sync(~0u, m, off));
                    float s = 0.f;
                    for (int d = lane; d < DD; d += 32) { float e = fastexp(row[d]-m); row[d] = e; s += e; }
#pragma unroll
                    for (int off = 16; off; off >>= 1) s += __shfl_xor_sync(~0u, s, off);
                    float inv = 1.f / s;
                    for (int d = lane; d < DD; d += 32)
                        prow[d] = __float2half_rn(row[d] * inv);
                }
                __syncthreads();
            }
            // ---- phase 2: O partial = P V^T (warp = ntile x khalf) ----
            int d0 = (ch-5)*320;
#pragma unroll
            for (int kst = 0; kst < 10; ++kst) {
                int dloc = khalf*160 + kst*16;
                uint32_t a[4];
                ldsm4(a, Pb + (uint32_t)(d0 + dloc)*2 + laneAp);
                uint32_t b[2];
                ldsm2(b, kvB + (uint32_t)(ntile*8)*656 + (uint32_t)dloc*2 + laneBv2);
                mma16(acc2, a, b[0], b[1]);
            }
        }
        __syncthreads();
        if (ch + 2 < 10) {
            stage(ch+2, ch & 1);
            asm volatile("cp.async.commit_group;" ::: "memory");
        }
    }
    __syncthreads();   // kv region free

    float* os  = (float*)((char*)smf + KV_OFF);   // [2*16][36]
    float* wsm = os + 2*16*36;                    // 4*1024
    float* bsm = wsm + 4096;                      // 4*32
    float* oq  = bsm + 128;                       // [16][33]

#pragma unroll
    for (int r = 0; r < 4; ++r) {
        int q = khalf*16 + gid + ((r >> 1) << 3);
        int c = ntile*8 + tig*2 + (r & 1);
        os[q*36 + c] = acc2[r];
    }
    for (int u = tid; u < 1024; u += 256) {
        int e = u >> 8, off = (u & 255)*4;
        const float* Wa = (e==0)?Wa_i:(e==1)?Wa_f:(e==2)?Wa_g:Wa_o;
        *reinterpret_cast<float4*>(wsm + e*1024 + off) =
            *reinterpret_cast<const float4*>(Wa + (size_t)g*1024 + off);
    }
    if (tid < 128) {
        int e = tid >> 5, c = tid & 31;
        const float* bb = (e==0)?b_i:(e==1)?b_f:(e==2)?b_g:b_o;
        bsm[tid] = bb[g*32 + c];
    }
    __syncthreads();

    for (int u = tid; u < 512; u += 256) {
        int q = u >> 5, c = u & 31;
        oq[q*33 + c] = os[q*36 + c] + os[(16+q)*36 + c];
    }
    __syncthreads();

    // fused gates + cell update
    for (int u = tid; u < 512; u += 256) {
        int q = u & 15, c = u >> 4;
        float a0 = bsm[c], a1 = bsm[32+c], a2 = bsm[64+c], a3 = bsm[96+c];
#pragma unroll 8
        for (int cc = 0; cc < 32; ++cc) {
            float o = oq[q*33 + cc];
            a0 = fmaf(wsm[        c*32 + cc], o, a0);
            a1 = fmaf(wsm[1024 + c*32 + cc], o, a1);
            a2 = fmaf(wsm[2048 + c*32 + cc], o, a2);
            a3 = fmaf(wsm[3072 + c*32 + cc], o, a3);
        }
        size_t off = ((size_t)(n*CCH) + g*32 + c)*HWQ + q0 + q;
        float gi = sigm (a0 + g_gp[0][off]);
        float gf = sigm (a1 + g_gp[1][off]);
        float gg = ftanh(a2 + g_gp[2][off]);
        float go = sigm (a3 + g_gp[3][off]);
        float cn = gf * c_prev[off] + gi * gg;
        outp[off] = go * ftanh(cn);
    }
}

// ---------------- launch ----------------------------------------------------
extern "C" void kernel_launch(void* const* d_in, const int* in_sizes, int n_in,
                              void* d_out, int out_size)
{
    (void)in_sizes; (void)n_in; (void)out_size;
    const float* inp    = (const float*)d_in[0];
    const float* h_prev = (const float*)d_in[1];
    const float* c_prev = (const float*)d_in[2];
    const float* Wx     = (const float*)d_in[3];
    const float* Wxg    = (const float*)d_in[4];
    const float* tau    = (const float*)d_in[5];
    const float* Wq     = (const float*)d_in[6];
    const float* Wk     = (const float*)d_in[7];
    const float* Wv     = (const float*)d_in[8];
    const float* Wa_i   = (const float*)d_in[9];
    const float* Wxh_i  = (const float*)d_in[10];
    const float* b_i    = (const float*)d_in[11];
    const float* Wa_f   = (const float*)d_in[12];
    const float* Wxh_f  = (const float*)d_in[13];
    const float* b_f    = (const float*)d_in[14];
    const float* Wa_g   = (const float*)d_in[15];
    const float* Wxh_g  = (const float*)d_in[16];
    const float* b_g    = (const float*)d_in[17];
    const float* Wa_o   = (const float*)d_in[18];
    const float* Wxh_o  = (const float*)d_in[19];
    const float* b_o    = (const float*)d_in[20];
    float* out = (float*)d_out;

    cudaFuncSetAttribute(attn_kernel,
                         cudaFuncAttributeMaxDynamicSharedMemorySize, ATTN_SMEM);
    cudaFuncSetAttribute(conv_same_kernel,
                         cudaFuncAttributeMaxDynamicSharedMemorySize, SMEM_S);
    cudaFuncSetAttribute(conv_valid_kernel,
                         cudaFuncAttributeMaxDynamicSharedMemorySize, SMEM_V);

    zero_xh2_kernel<<<2048, 256>>>();
    wtrans_kernel<<<GG*224, 256>>>(Wq, Wxh_i, Wxh_f, Wxh_g, Wxh_o, Wk, Wv);
    proj_kernel<<<dim3(9, 32, 4), 256>>>(inp, h_prev, Wx, Wxg);
    conv_same_kernel<<<dim3(9, 8, 4), 256, SMEM_S>>>();
    conv_valid_kernel<<<dim3(9, 8, 2), 256, SMEM_V>>>();
    attn_kernel<<<NN*GG*144, 256, ATTN_SMEM>>>(tau, Wa_i, Wa_f, Wa_g, Wa_o,
                                               b_i, b_f, b_g, b_o, c_prev, out);
}

// round 17
// speedup vs baseline: 1.0845x; 1.0267x over previous
#include <cuda_runtime.h>
#include <cuda_fp16.h>
#include <cstdint>
#include <math.h>

// Problem constants
#define NN   4
#define II   64
#define CCH  256
#define GG   8
#define CG   32
#define KS   9
#define HH   48
#define HWQ  (48*48)   // 2304
#define HD   40
#define DD   (40*40)   // 1600
#define PW   56
#define PHW  (56*56)

// ---------------- scratch (device globals; no allocation allowed) -----------
__device__ __align__(128) __half g_xh2[NN*GG*PHW*64];
__device__ __align__(128) __half g_wS[GG*81*160*64];
__device__ __align__(128) __half g_wV[GG*81*64*64];
__device__ __align__(128) __half g_q16[NN*CCH*HWQ];       // [n][c][q]
__device__ __align__(128) __half g_k16[NN*GG*DD*32];      // [n][g][d][c]
__device__ __align__(128) __half g_v16[NN*CCH*DD];        // [n][c][d]
__device__ __align__(128) float g_gp[4][NN*CCH*HWQ];

// FFMA-only exp for softmax
__device__ __forceinline__ float fastexp(float x) {
    float z = fmaxf(x * 1.4426950408889634f, -120.f);
    float t = z + 12582912.f;
    int   e = __float_as_int(t) - 0x4B400000;
    float f = z - (t - 12582912.f);
    float p = fmaf(f, 0.0013333558f, 0.0096181291f);
    p = fmaf(f, p, 0.0555041087f);
    p = fmaf(f, p, 0.2402265069f);
    p = fmaf(f, p, 0.69314718056f);
    p = fmaf(f, p, 1.0f);
    return __int_as_float(__float_as_int(p) + (e << 23));
}
__device__ __forceinline__ float ftanh(float x) {
    float t; asm("tanh.approx.f32 %0, %1;" : "=f"(t) : "f"(x)); return t;
}
__device__ __forceinline__ float sigm(float x) {
    return fmaf(ftanh(x * 0.5f), 0.5f, 0.5f);
}

// m16n8k16 fp16 mma.sync with fp32 accumulate
__device__ __forceinline__ void mma16(float* c, const uint32_t* a,
                                      uint32_t b0, uint32_t b1) {
    asm volatile(
        "mma.sync.aligned.m16n8k16.row.col.f32.f16.f16.f32 "
        "{%0,%1,%2,%3}, {%4,%5,%6,%7}, {%8,%9}, {%0,%1,%2,%3};"
        : "+f"(c[0]), "+f"(c[1]), "+f"(c[2]), "+f"(c[3])
        : "r"(a[0]), "r"(a[1]), "r"(a[2]), "r"(a[3]), "r"(b0), "r"(b1));
}
__device__ __forceinline__ void ldsm4(uint32_t* r, uint32_t addr) {
    asm volatile("ldmatrix.sync.aligned.m8n8.x4.shared.b16 {%0,%1,%2,%3}, [%4];"
        : "=r"(r[0]), "=r"(r[1]), "=r"(r[2]), "=r"(r[3]) : "r"(addr));
}
__device__ __forceinline__ void ldsm2(uint32_t* r, uint32_t addr) {
    asm volatile("ldmatrix.sync.aligned.m8n8.x2.shared.b16 {%0,%1}, [%2];"
        : "=r"(r[0]), "=r"(r[1]) : "r"(addr));
}
__device__ __forceinline__ void cp16(uint32_t dst, const void* src) {
    asm volatile("cp.async.cg.shared.global [%0], [%1], 16;" :: "r"(dst), "l"(src));
}
__device__ __forceinline__ uint32_t smem_u32(const void* p) {
    uint32_t a;
    asm("{ .reg .u64 t; cvta.to.shared.u64 t, %1; cvt.u32.u64 %0, t; }" : "=r"(a) : "l"(p));
    return a;
}

// ---------------- 0: zero ONLY the 4-wide halo of xh2 ------------------------
// Per (n,g): 832 border positions of 56x56, 64 ch each (128 B per position).
__global__ __launch_bounds__(256)
void zero_border_kernel() {
    int idx = blockIdx.x*blockDim.x + threadIdx.x;   // over 32*832
    if (idx >= 32*832) return;
    int ng = idx / 832, u = idx - ng*832;
    int y, x;
    if (u < 448) { int r = u / 56; y = (r < 4) ? r : r + 48; x = u % 56; }
    else         { int v = u - 448; y = 4 + (v >> 3); int c = v & 7; x = (c < 4) ? c : c + 44; }
    uint4* p = reinterpret_cast<uint4*>(g_xh2 + ((size_t)ng*PHW + y*PW + x)*64);
#pragma unroll
    for (int j = 0; j < 8; ++j) p[j] = make_uint4(0u,0u,0u,0u);
}

// ---------------- 0b: weight transpose via smem tile (coalesced, fp16) ------
__global__ __launch_bounds__(256)
void wtrans_kernel(const float* __restrict__ Wq, const float* __restrict__ Wi,
                   const float* __restrict__ Wf, const float* __restrict__ Wg,
                   const float* __restrict__ Wo, const float* __restrict__ Wk,
                   const float* __restrict__ Wv)
{
    __shared__ float sm[5184];
    int b = blockIdx.x;          // 0..1791
    int g = b / 224;
    int r = b % 224;
    int tid = threadIdx.x;

    const float* W;
    __half* dst;
    int row, NCr, rr;
    if (r < 160) {
        int j = r >> 5;
        W = (j==0)?Wq:(j==1)?Wi:(j==2)?Wf:(j==3)?Wg:Wo;
        row = r & 31; dst = g_wS; NCr = 160; rr = r;
    } else {
        int r2 = r - 160;
        W = (r2 < 32) ? Wk : Wv;
        row = r2 & 31; dst = g_wV; NCr = 64; rr = r2;
    }
    const float* src = W + (size_t)(g*32 + row)*5184;
    for (int u = tid; u < 5184; u += 256) sm[u] = src[u];
    __syncthreads();
    for (int u = tid; u < 5184; u += 256) {
        int k = u >> 6, ci = u & 63;
        dst[((size_t)(g*81 + k)*NCr + rr)*64 + ci] = __float2half_rn(sm[ci*81 + k]);
    }
}

// ---------------- 1: projection + build padded channel-last xh (fp16) -------
__global__ __launch_bounds__(256)
void proj_kernel(const float* __restrict__ inp, const float* __restrict__ h,
                 const float* __restrict__ Wx, const float* __restrict__ Wxg)
{
    __shared__ float ws[8*320];
    int n  = blockIdx.z;
    int c0 = blockIdx.y * 8;
    int p0 = blockIdx.x * 256;
    int tid = threadIdx.x;

    for (int idx = tid; idx < 8*320; idx += 256) {
        int j = idx / 320, ic = idx - j*320;
        ws[idx] = (ic < 64) ? Wx[(c0+j)*64 + ic] : Wxg[(c0+j)*256 + (ic-64)];
    }
    __syncthreads();

    int p = p0 + tid;
    float acc[8];
#pragma unroll
    for (int j = 0; j < 8; ++j) acc[j] = 0.f;

    const float* ib = inp + (size_t)n*II*HWQ + p;
    const float* hb = h   + (size_t)n*CCH*HWQ + p;

#pragma unroll 4
    for (int ic = 0; ic < 64; ++ic) {
        float v = ib[ic*HWQ];
#pragma unroll
        for (int j = 0; j < 8; ++j) acc[j] = fmaf(ws[j*320+ic], v, acc[j]);
    }
#pragma unroll 4
    for (int ic = 0; ic < 256; ++ic) {
        float v = hb[ic*HWQ];
#pragma unroll
        for (int j = 0; j < 8; ++j) acc[j] = fmaf(ws[j*320+64+ic], v, acc[j]);
    }

    int y = p / 48, x = p - y*48;
    int g = c0 >> 5;
    __half* xb = g_xh2 + ((size_t)(n*GG + g)*PHW + (y+4)*PW + (x+4))*64;
#pragma unroll
    for (int j = 0; j < 8; ++j) {
        int cg = (c0 + j) & 31;
        xb[cg]      = __float2half_rn(acc[j]);
        xb[32 + cg] = __float2half_rn(hb[(c0+j)*HWQ]);
    }
}

// ---------------- 2a: SAME grouped conv, fp16 mma + ldmatrix, CK=64 ---------
#define ITH (24*24*72)
#define SMEM_S (ITH*2 + 3*160*72*2)   // 152064
__global__ __launch_bounds__(256, 1)
void conv_same_kernel()
{
    extern __shared__ __half smh[];
    __half* IT = smh;

    const int tid = threadIdx.x;
    const int wid = tid >> 5, lane = tid & 31;
    const int gid = lane >> 2, tig = lane & 3;
    const int my0 = (wid >> 1) * 4;
    const int nb  = (wid & 1) * 80;

    const int g  = blockIdx.y;
    const int n  = blockIdx.z;
    const int x0 = (blockIdx.x % 3) * 16;
    const int y0 = (blockIdx.x / 3) * 16;

    float* outs[5] = {nullptr, g_gp[0], g_gp[1], g_gp[2], g_gp[3]};

    const __half* xsrc = g_xh2 + (size_t)(n*GG + g)*PHW*64;
    const __half* wg   = g_wS + (size_t)g*81*160*64;
    const uint32_t itb   = smem_u32(smh);
    const uint32_t smemB = itb + ITH*2;

    const uint32_t laneA  = 2u * ((((lane >> 3) & 1)*8 + (lane & 7))*72 + (lane >> 4)*8);
    const uint32_t laneB7 = 2u * ((((lane >> 4) & 1)*8 + (lane & 7))*72 + ((lane >> 3) & 1)*8);

    auto stageB = [&](int t, int buf) {
        const __half* wsrc = wg + (size_t)t*160*64;
        uint32_t bbase = smemB + (uint32_t)buf*(160*72*2);
        for (int u = tid; u < 160*8; u += 256) {
            int n2 = u >> 3, seg = u & 7;
            cp16(bbase + (uint32_t)(n2*144 + seg*16), wsrc + n2*64 + seg*8);
        }
    };

    stageB(0, 0);
    asm volatile("cp.async.commit_group;" ::: "memory");
    stageB(1, 1);
    asm volatile("cp.async.commit_group;" ::: "memory");

    for (int u = tid; u < 24*24*8; u += 256) {
        int f4 = u & 7, pos = u >> 3;
        int yy = pos / 24, xx = pos - yy*24;
        int gy = min(y0 + yy, 55), gx = min(x0 + xx, 55);
        float4 v = *reinterpret_cast<const float4*>(xsrc + (size_t)(gy*PW + gx)*64 + f4*8);
        *reinterpret_cast<float4*>(IT + pos*72 + f4*8) = v;
    }

    float acc[4][10][4];
#pragma unroll
    for (int mi = 0; mi < 4; ++mi)
#pragma unroll
        for (int nj = 0; nj < 10; ++nj)
#pragma unroll
            for (int r = 0; r < 4; ++r) acc[mi][nj][r] = 0.f;

    for (int t = 0; t < 81; ++t) {
        if (t == 80) asm volatile("cp.async.wait_group 0;" ::: "memory");
        else         asm volatile("cp.async.wait_group 1;" ::: "memory");
        __syncthreads();
        if (t + 2 < 81) {
            stageB(t+2, (t+2) % 3);
            asm volatile("cp.async.commit_group;" ::: "memory");
        }

        const int ky = t / 9, kx = t - ky*9;
        const uint32_t bB = smemB + (uint32_t)(t % 3)*(160*72*2);

#pragma unroll
        for (int ks = 0; ks < 4; ++ks) {
            const int kh0 = ks*16;
            uint32_t a[4][4];
#pragma unroll
            for (int mi = 0; mi < 4; ++mi)
                ldsm4(a[mi], itb + 2u*(uint32_t)(((my0 + mi + ky)*24 + kx)*72 + kh0) + laneA);
#pragma unroll
            for (int nj2 = 0; nj2 < 5; ++nj2) {
                uint32_t b[4];
                ldsm4(b, bB + 2u*(uint32_t)((nb + nj2*16)*72 + ks*16) + laneB7);
#pragma unroll
                for (int mi = 0; mi < 4; ++mi) {
                    mma16(acc[mi][2*nj2],   a[mi], b[0], b[1]);
                    mma16(acc[mi][2*nj2+1], a[mi], b[2], b[3]);
                }
            }
        }
    }

#pragma unroll
    for (int mi = 0; mi < 4; ++mi) {
        int y = y0 + my0 + mi;
#pragma unroll
        for (int nj = 0; nj < 10; ++nj)
#pragma unroll
            for (int r = 0; r < 4; ++r) {
                int x = x0 + gid + ((r >> 1) << 3);
                int nc = nb + nj*8 + tig*2 + (r & 1);
                int conv = nc >> 5, cg = nc & 31;
                if (conv == 0)
                    g_q16[((size_t)(n*CCH + g*32 + cg)*48 + y)*48 + x] =
                        __float2half_rn(acc[mi][nj][r]);
                else
                    outs[conv][((size_t)(n*CCH + g*32 + cg)*48 + y)*48 + x] = acc[mi][nj][r];
            }
    }
}

// ---------------- 2b: VALID grouped conv (k, v), fp16, CK=64 (81 iters) -----
#define SMEM_V (2*ITH*2 + 3*64*72*2)  // 193536
__global__ __launch_bounds__(256, 1)
void conv_valid_kernel()
{
    extern __shared__ __half smh[];

    const int tid = threadIdx.x;
    const int wid = tid >> 5, lane = tid & 31;
    const int gid = lane >> 2, tig = lane & 3;
    const int bw  = wid >> 2;
    const int my0 = (wid & 3) * 4;

    const int g  = blockIdx.y;
    const int n0 = blockIdx.z * 2;
    const int x0 = (blockIdx.x % 3) * 16;
    const int y0 = (blockIdx.x / 3) * 16;

    const __half* wg = g_wV + (size_t)g*81*64*64;
    const uint32_t smb   = smem_u32(smh);
    const uint32_t smemB = smb + 2*ITH*2;

    const uint32_t laneA  = 2u * ((((lane >> 3) & 1)*8 + (lane & 7))*72 + (lane >> 4)*8);
    const uint32_t laneB7 = 2u * ((((lane >> 4) & 1)*8 + (lane & 7))*72 + ((lane >> 3) & 1)*8);

    auto stageB = [&](int t, int buf) {
        const __half* wsrc = wg + (size_t)t*64*64;
        uint32_t bbase = smemB + (uint32_t)buf*(64*72*2);
        for (int u = tid; u < 64*8; u += 256) {
            int n2 = u >> 3, seg = u & 7;
            cp16(bbase + (uint32_t)(n2*144 + seg*16), wsrc + n2*64 + seg*8);
        }
    };

    stageB(0, 0);
    asm volatile("cp.async.commit_group;" ::: "memory");
    stageB(1, 1);
    asm volatile("cp.async.commit_group;" ::: "memory");

    for (int u = tid; u < 2*24*24*8; u += 256) {
        int b2 = u / (24*24*8);
        int u2 = u - b2*(24*24*8);
        int f4 = u2 & 7, pos = u2 >> 3;
        int yy = pos / 24, xx = pos - yy*24;
        int gy = min(y0 + 4 + yy, 55), gx = min(x0 + 4 + xx, 55);
        const __half* xsrc = g_xh2 + (size_t)((n0+b2)*GG + g)*PHW*64;
        float4 v = *reinterpret_cast<const float4*>(xsrc + (size_t)(gy*PW + gx)*64 + f4*8);
        *reinterpret_cast<float4*>(smh + b2*ITH + pos*72 + f4*8) = v;
    }

    const uint32_t itb = smb + (uint32_t)bw*ITH*2;

    float acc[4][8][4];
#pragma unroll
    for (int mi = 0; mi < 4; ++mi)
#pragma unroll
        for (int nj = 0; nj < 8; ++nj)
#pragma unroll
            for (int r = 0; r < 4; ++r) acc[mi][nj][r] = 0.f;

    for (int t = 0; t < 81; ++t) {
        if (t == 80) asm volatile("cp.async.wait_group 0;" ::: "memory");
        else         asm volatile("cp.async.wait_group 1;" ::: "memory");
        __syncthreads();
        if (t + 2 < 81) {
            stageB(t+2, (t+2) % 3);
            asm volatile("cp.async.commit_group;" ::: "memory");
        }

        const int ky = t / 9, kx = t - ky*9;
        const uint32_t bB = smemB + (uint32_t)(t % 3)*(64*72*2);

#pragma unroll
        for (int ks = 0; ks < 4; ++ks) {
            const int kh0 = ks*16;
            uint32_t a[4][4];
#pragma unroll
            for (int mi = 0; mi < 4; ++mi)
                ldsm4(a[mi], itb + 2u*(uint32_t)(((my0 + mi + ky)*24 + kx)*72 + kh0) + laneA);
#pragma unroll
            for (int nj2 = 0; nj2 < 4; ++nj2) {
                uint32_t b[4];
                ldsm4(b, bB + 2u*(uint32_t)((nj2*16)*72 + ks*16) + laneB7);
#pragma unroll
                for (int mi = 0; mi < 4; ++mi) {
                    mma16(acc[mi][2*nj2],   a[mi], b[0], b[1]);
                    mma16(acc[mi][2*nj2+1], a[mi], b[2], b[3]);
                }
            }
        }
    }

    const int n = n0 + bw;
#pragma unroll
    for (int mi = 0; mi < 4; ++mi) {
        int y = y0 + my0 + mi;
        if (y >= 40) continue;
#pragma unroll
        for (int nj = 0; nj < 8; ++nj)
#pragma unroll
            for (int r = 0; r < 4; ++r) {
                int x = x0 + gid + ((r >> 1) << 3);
                if (x < 40) {
                    int nc = nj*8 + tig*2 + (r & 1);
                    int cg = nc & 31;
                    int d = y*40 + x;
                    if (nc < 32)   // k -> [n][g][d][c]
                        g_k16[((size_t)(n*GG + g)*DD + d)*32 + cg] =
                            __float2half_rn(acc[mi][nj][r]);
                    else           // v -> [n][c][d]
                        g_v16[((size_t)(n*CCH) + g*32 + cg)*DD + d] =
                            __float2half_rn(acc[mi][nj][r]);
                }
            }
    }
}

// ---------------- 3: attention fp16 mma + fused gates ------------------------
#define LSP   1604                 // fp32 logits stride (floats)
#define PSTR  1608                 // fp16 P stride (halves)
#define KVBUF 25600                // bytes per kv buffer
#define LS_BYTES   (16*LSP*4)
#define P_OFF      LS_BYTES
#define QS_OFF     (P_OFF + 16*PSTR*2)
#define KV_OFF     (QS_OFF + 16*40*2)
#define ATTN_SMEM  (KV_OFF + 2*KVBUF)       // 206592

__global__ __launch_bounds__(256)
void attn_kernel(const float* __restrict__ tau,
                 const float* __restrict__ Wa_i, const float* __restrict__ Wa_f,
                 const float* __restrict__ Wa_g, const float* __restrict__ Wa_o,
                 const float* __restrict__ b_i,  const float* __restrict__ b_f,
                 const float* __restrict__ b_g,  const float* __restrict__ b_o,
                 const float* __restrict__ c_prev, float* __restrict__ outp)
{
    extern __shared__ float smf[];
    float*  ls = smf;
    __half* Pp = (__half*)((char*)smf + P_OFF);
    __half* qs = (__half*)((char*)smf + QS_OFF);

    int bz = blockIdx.x;
    int qt = bz % 144;
    int g  = (bz / 144) & 7;
    int n  = bz / 1152;
    int q0 = qt * 16;

    const __half* qb = g_q16 + ((size_t)(n*CCH) + g*32)*HWQ + q0;
    const __half* kb = g_k16 + (size_t)(n*GG + g)*DD*32;
    const __half* vb = g_v16 + ((size_t)(n*CCH) + g*32)*DD;
    int tid = threadIdx.x;
    int wid = tid >> 5, lane = tid & 31;
    int gid = lane >> 2, tig = lane & 3;

    const uint32_t smb    = smem_u32(smf);
    const uint32_t Pb     = smb + P_OFF;
    const uint32_t qsb    = smb + QS_OFF;
    const uint32_t kvbase = smb + KV_OFF;

    const uint32_t laneAq = 2u*((((lane>>3)&1)*8 + (lane&7))*40   + (lane>>4)*8);
    const uint32_t laneAp = 2u*((((lane>>3)&1)*8 + (lane&7))*1608 + (lane>>4)*8);
    const uint32_t laneBk = 2u*((((lane>>4)&1)*8 + (lane&7))*40   + ((lane>>3)&1)*8);
    const int      l15    = lane & 15;
    const uint32_t laneBk2= 2u*((l15&7)*40  + ((l15>>3)&1)*8);
    const uint32_t laneBv2= 2u*((l15&7)*328 + ((l15>>3)&1)*8);

    auto stage = [&](int c, int buf) {
        uint32_t bbase = kvbase + (uint32_t)buf*KVBUF;
        if (c < 5) {
            const __half* src = kb + (size_t)(c*320)*32;
            for (int u = tid; u < 1280; u += 256) {
                int dd = u >> 2, seg = u & 3;
                cp16(bbase + (uint32_t)(dd*80 + seg*16), src + dd*32 + seg*8);
            }
        } else {
            const __half* src = vb + (c-5)*320;
            for (int u = tid; u < 1280; u += 256) {
                int cc = u / 40, seg = u % 40;
                cp16(bbase + (uint32_t)(cc*656 + seg*16), src + (size_t)cc*DD + seg*8);
            }
        }
    };

    stage(0, 0);
    asm volatile("cp.async.commit_group;" ::: "memory");
    stage(1, 1);
    asm volatile("cp.async.commit_group;" ::: "memory");

    for (int idx = tid; idx < 512; idx += 256) {
        int qi = idx >> 5, c = idx & 31;
        qs[qi*40 + c] = qb[c*HWQ + qi];
    }
    float tg = tau[g];

    uint32_t aq[2][4];
    float acc2[4];
#pragma unroll
    for (int r = 0; r < 4; ++r) acc2[r] = 0.f;

    const int ntile = wid & 3, khalf = wid >> 2;

    for (int ch = 0; ch < 10; ++ch) {
        if (ch == 9) asm volatile("cp.async.wait_group 0;" ::: "memory");
        else         asm volatile("cp.async.wait_group 1;" ::: "memory");
        __syncthreads();

        uint32_t kvB = kvbase + (uint32_t)(ch & 1)*KVBUF;

        if (ch == 0) {
            ldsm4(aq[0], qsb + laneAq);
            ldsm4(aq[1], qsb + 32 + laneAq);
        }

        if (ch < 5) {
            int d0 = ch*320;
            int nw = wid*40;
            float acc[5][4];
#pragma unroll
            for (int nj = 0; nj < 5; ++nj)
#pragma unroll
                for (int r = 0; r < 4; ++r) acc[nj][r] = 0.f;

#pragma unroll
            for (int gt = 0; gt < 2; ++gt) {
                uint32_t b0[4], b1[4];
                uint32_t base = kvB + (uint32_t)(nw + gt*16)*80;
                ldsm4(b0, base + laneBk);
                ldsm4(b1, base + 32 + laneBk);
                mma16(acc[gt*2],   aq[0], b0[0], b0[1]);
                mma16(acc[gt*2],   aq[1], b1[0], b1[1]);
                mma16(acc[gt*2+1], aq[0], b0[2], b0[3]);
                mma16(acc[gt*2+1], aq[1], b1[2], b1[3]);
            }
            {
                uint32_t b0[2], b1[2];
                uint32_t base = kvB + (uint32_t)(nw + 32)*80;
                ldsm2(b0, base + laneBk2);
                ldsm2(b1, base + 32 + laneBk2);
                mma16(acc[4], aq[0], b0[0], b0[1]);
                mma16(acc[4], aq[1], b1[0], b1[1]);
            }
#pragma unroll
            for (int nj = 0; nj < 5; ++nj) {
                int d = d0 + nw + nj*8 + 2*tig;
                float2 lo = make_float2(acc[nj][0]*tg, acc[nj][1]*tg);
                float2 hi = make_float2(acc[nj][2]*tg, acc[nj][3]*tg);
                *reinterpret_cast<float2*>(ls + gid*LSP     + d) = lo;
                *reinterpret_cast<float2*>(ls + (gid+8)*LSP + d) = hi;
            }
        } else {
            if (ch == 5) {
                for (int q = wid; q < 16; q += 8) {
                    float* row = ls + q*LSP;
                    __half* prow = Pp + q*PSTR;
                    float m = -1e30f;
                    for (int d = lane; d < DD; d += 32) m = fmaxf(m, row[d]);
#pragma unroll
                    for (int off = 16; off; off >>= 1) m = fmaxf(m, __shfl_xor_sync(~0u, m, off));
                    float s = 0.f;
                    for (int d = lane; d < DD; d += 32) { float e = fastexp(row[d]-m); row[d] = e; s += e; }
#pragma unroll
                    for (int off = 16; off; off >>= 1) s += __shfl_xor_sync(~0u, s, off);
                    float inv = 1.f / s;
                    for (int d = lane; d < DD; d += 32)
                        prow[d] = __float2half_rn(row[d] * inv);
                }
                __syncthreads();
            }
            int d0 = (ch-5)*320;
#pragma unroll
            for (int kst = 0; kst < 10; ++kst) {
                int dloc = khalf*160 + kst*16;
                uint32_t a[4];
                ldsm4(a, Pb + (uint32_t)(d0 + dloc)*2 + laneAp);
                uint32_t b[2];
                ldsm2(b, kvB + (uint32_t)(ntile*8)*656 + (uint32_t)dloc*2 + laneBv2);
                mma16(acc2, a, b[0], b[1]);
            }
        }
        __syncthreads();
        if (ch + 2 < 10) {
            stage(ch+2, ch & 1);
            asm volatile("cp.async.commit_group;" ::: "memory");
        }
    }
    __syncthreads();

    float* os  = (float*)((char*)smf + KV_OFF);   // [2*16][36]
    float* wsm = os + 2*16*36;                    // 4*1024
    float* bsm = wsm + 4096;                      // 4*32
    float* oq  = bsm + 128;                       // [16][33]

#pragma unroll
    for (int r = 0; r < 4; ++r) {
        int q = khalf*16 + gid + ((r >> 1) << 3);
        int c = ntile*8 + tig*2 + (r & 1);
        os[q*36 + c] = acc2[r];
    }
    for (int u = tid; u < 1024; u += 256) {
        int e = u >> 8, off = (u & 255)*4;
        const float* Wa = (e==0)?Wa_i:(e==1)?Wa_f:(e==2)?Wa_g:Wa_o;
        *reinterpret_cast<float4*>(wsm + e*1024 + off) =
            *reinterpret_cast<const float4*>(Wa + (size_t)g*1024 + off);
    }
    if (tid < 128) {
        int e = tid >> 5, c = tid & 31;
        const float* bb = (e==0)?b_i:(e==1)?b_f:(e==2)?b_g:b_o;
        bsm[tid] = bb[g*32 + c];
    }
    __syncthreads();

    for (int u = tid; u < 512; u += 256) {
        int q = u >> 5, c = u & 31;
        oq[q*33 + c] = os[q*36 + c] + os[(16+q)*36 + c];
    }
    __syncthreads();

    for (int u = tid; u < 512; u += 256) {
        int q = u & 15, c = u >> 4;
        float a0 = bsm[c], a1 = bsm[32+c], a2 = bsm[64+c], a3 = bsm[96+c];
#pragma unroll 8
        for (int cc = 0; cc < 32; ++cc) {
            float o = oq[q*33 + cc];
            a0 = fmaf(wsm[        c*32 + cc], o, a0);
            a1 = fmaf(wsm[1024 + c*32 + cc], o, a1);
            a2 = fmaf(wsm[2048 + c*32 + cc], o, a2);
            a3 = fmaf(wsm[3072 + c*32 + cc], o, a3);
        }
        size_t off = ((size_t)(n*CCH) + g*32 + c)*HWQ + q0 + q;
        float gi = sigm (a0 + g_gp[0][off]);
        float gf = sigm (a1 + g_gp[1][off]);
        float gg = ftanh(a2 + g_gp[2][off]);
        float go = sigm (a3 + g_gp[3][off]);
        float cn = gf * c_prev[off] + gi * gg;
        outp[off] = go * ftanh(cn);
    }
}

// ---------------- launch ----------------------------------------------------
extern "C" void kernel_launch(void* const* d_in, const int* in_sizes, int n_in,
                              void* d_out, int out_size)
{
    (void)in_sizes; (void)n_in; (void)out_size;
    const float* inp    = (const float*)d_in[0];
    const float* h_prev = (const float*)d_in[1];
    const float* c_prev = (const float*)d_in[2];
    const float* Wx     = (const float*)d_in[3];
    const float* Wxg    = (const float*)d_in[4];
    const float* tau    = (const float*)d_in[5];
    const float* Wq     = (const float*)d_in[6];
    const float* Wk     = (const float*)d_in[7];
    const float* Wv     = (const float*)d_in[8];
    const float* Wa_i   = (const float*)d_in[9];
    const float* Wxh_i  = (const float*)d_in[10];
    const float* b_i    = (const float*)d_in[11];
    const float* Wa_f   = (const float*)d_in[12];
    const float* Wxh_f  = (const float*)d_in[13];
    const float* b_f    = (const float*)d_in[14];
    const float* Wa_g   = (const float*)d_in[15];
    const float* Wxh_g  = (const float*)d_in[16];
    const float* b_g    = (const float*)d_in[17];
    const float* Wa_o   = (const float*)d_in[18];
    const float* Wxh_o  = (const float*)d_in[19];
    const float* b_o    = (const float*)d_in[20];
    float* out = (float*)d_out;

    cudaFuncSetAttribute(attn_kernel,
                         cudaFuncAttributeMaxDynamicSharedMemorySize, ATTN_SMEM);
    cudaFuncSetAttribute(conv_same_kernel,
                         cudaFuncAttributeMaxDynamicSharedMemorySize, SMEM_S);
    cudaFuncSetAttribute(conv_valid_kernel,
                         cudaFuncAttributeMaxDynamicSharedMemorySize, SMEM_V);

    zero_border_kernel<<<(32*832 + 255)/256, 256>>>();
    wtrans_kernel<<<GG*224, 256>>>(Wq, Wxh_i, Wxh_f, Wxh_g, Wxh_o, Wk, Wv);
    proj_kernel<<<dim3(9, 32, 4), 256>>>(inp, h_prev, Wx, Wxg);
    conv_same_kernel<<<dim3(9, 8, 4), 256, SMEM_S>>>();
    conv_valid_kernel<<<dim3(9, 8, 2), 256, SMEM_V>>>();
    attn_kernel<<<NN*GG*144, 256, ATTN_SMEM>>>(tau, Wa_i, Wa_f, Wa_g, Wa_o,
                                               b_i, b_f, b_g, b_o, c_prev, out);
}